// round 6
// baseline (speedup 1.0000x reference)
#include <cuda_runtime.h>
#include <cuda_bf16.h>
#include <cstdint>
#include <math.h>

// Problem: B=2, S=2048, HID=2048, H=32, KVH=8, D=64, G=4, ROT=32
#define NBATCH 2
#define SEQ    2048
#define HID    2048
#define NHEAD  32
#define NKV    8
#define HDIM   64

// ---------------------------------------------------------------------------
// Scratch (device globals; no allocations allowed)
// ---------------------------------------------------------------------------
__device__ float g_q[NBATCH*SEQ*NHEAD*HDIM];
__device__ float g_k[NBATCH*SEQ*NKV*HDIM];
__device__ float g_v[NBATCH*SEQ*NKV*HDIM];

__device__ __nv_bfloat16 g_ah[4096*2048], g_al[4096*2048];     // hidden
__device__ __nv_bfloat16 g_oh[4096*2048], g_ol[4096*2048];     // attn out
__device__ __nv_bfloat16 g_wqh[2048*2048], g_wql[2048*2048];
__device__ __nv_bfloat16 g_wkh[512*2048],  g_wkl[512*2048];
__device__ __nv_bfloat16 g_wvh[512*2048],  g_wvl[512*2048];
__device__ __nv_bfloat16 g_woh[2048*2048], g_wol[2048*2048];
__device__ __nv_bfloat16 g_qh[NBATCH*SEQ*NHEAD*HDIM], g_ql[NBATCH*SEQ*NHEAD*HDIM];
__device__ __nv_bfloat16 g_kh[NBATCH*SEQ*NKV*HDIM],   g_kl[NBATCH*SEQ*NKV*HDIM];
__device__ __nv_bfloat16 g_vht[NBATCH*NKV*HDIM*SEQ],  g_vlt[NBATCH*NKV*HDIM*SEQ];

// ---------------------------------------------------------------------------
// helpers
// ---------------------------------------------------------------------------
__device__ __forceinline__ uint32_t smem_u32(const void* p) {
    uint32_t a;
    asm("{ .reg .u64 t; cvta.to.shared.u64 t, %1; cvt.u32.u64 %0, t; }"
        : "=r"(a) : "l"(p));
    return a;
}
__device__ __forceinline__ void mma_bf16(float* c, const uint32_t* a,
                                         uint32_t b0, uint32_t b1) {
    asm volatile(
        "mma.sync.aligned.m16n8k16.row.col.f32.bf16.bf16.f32 "
        "{%0,%1,%2,%3}, {%4,%5,%6,%7}, {%8,%9}, {%0,%1,%2,%3};"
        : "+f"(c[0]), "+f"(c[1]), "+f"(c[2]), "+f"(c[3])
        : "r"(a[0]), "r"(a[1]), "r"(a[2]), "r"(a[3]), "r"(b0), "r"(b1));
}
__device__ __forceinline__ void ldmx4(uint32_t* r, uint32_t saddr) {
    asm volatile("ldmatrix.sync.aligned.m8n8.x4.shared.b16 {%0,%1,%2,%3}, [%4];"
        : "=r"(r[0]), "=r"(r[1]), "=r"(r[2]), "=r"(r[3]) : "r"(saddr));
}
__device__ __forceinline__ void cp_async16(void* smem_dst, const void* gsrc) {
    uint32_t d;
    asm("{ .reg .u64 t; cvta.to.shared.u64 t, %1; cvt.u32.u64 %0, t; }"
        : "=r"(d) : "l"(smem_dst));
    asm volatile("cp.async.cg.shared.global [%0], [%1], 16;" :: "r"(d), "l"(gsrc));
}
#define CP_COMMIT() asm volatile("cp.async.commit_group;" ::: "memory")
#define CP_WAIT(n)  asm volatile("cp.async.wait_group %0;" :: "n"(n) : "memory")

// ---------------------------------------------------------------------------
// fp32 -> (bf16 hi, bf16 lo) split
// ---------------------------------------------------------------------------
__global__ void split_kernel(const float* __restrict__ x,
                             __nv_bfloat16* __restrict__ hi,
                             __nv_bfloat16* __restrict__ lo, int n4) {
    int i = blockIdx.x * blockDim.x + threadIdx.x;
    if (i >= n4) return;
    float4 v = ((const float4*)x)[i];
    __nv_bfloat16 h0 = __float2bfloat16(v.x);
    __nv_bfloat16 h1 = __float2bfloat16(v.y);
    __nv_bfloat16 h2 = __float2bfloat16(v.z);
    __nv_bfloat16 h3 = __float2bfloat16(v.w);
    __nv_bfloat162* hp = (__nv_bfloat162*)(hi + (size_t)i * 4);
    __nv_bfloat162* lp = (__nv_bfloat162*)(lo + (size_t)i * 4);
    hp[0] = __nv_bfloat162(h0, h1); hp[1] = __nv_bfloat162(h2, h3);
    lp[0] = __nv_bfloat162(__float2bfloat16(v.x - __bfloat162float(h0)),
                           __float2bfloat16(v.y - __bfloat162float(h1)));
    lp[1] = __nv_bfloat162(__float2bfloat16(v.z - __bfloat162float(h2)),
                           __float2bfloat16(v.w - __bfloat162float(h3)));
}

// ---------------------------------------------------------------------------
// Fused partial-RoPE + scale + bf16 hi/lo split.
// x fp32 [bs][nheads][64]; one thread per 4-elem quad.
// ---------------------------------------------------------------------------
__global__ void rope_split_kernel(const float* __restrict__ x,
                                  const float* __restrict__ ct,
                                  const float* __restrict__ st,
                                  __nv_bfloat16* __restrict__ hi,
                                  __nv_bfloat16* __restrict__ lo,
                                  int nheads, int total4, float scale) {
    int idx = blockIdx.x * blockDim.x + threadIdx.x;
    if (idx >= total4) return;
    int qd = idx & 15;
    int bs = idx / (16 * nheads);
    float4 v = ((const float4*)x)[idx];
    float4 o = v;
    if (qd < 8) {
        int d0 = qd * 4;
        float4 p = ((const float4*)x)[idx + (qd < 4 ? 4 : -4)];
        const float* cb = ct + bs * 32 + d0;
        const float* sb = st + bs * 32 + d0;
        if (qd < 4) {
            o.x = v.x * cb[0] - p.x * sb[0];
            o.y = v.y * cb[1] - p.y * sb[1];
            o.z = v.z * cb[2] - p.z * sb[2];
            o.w = v.w * cb[3] - p.w * sb[3];
        } else {
            o.x = v.x * cb[0] + p.x * sb[0];
            o.y = v.y * cb[1] + p.y * sb[1];
            o.z = v.z * cb[2] + p.z * sb[2];
            o.w = v.w * cb[3] + p.w * sb[3];
        }
    }
    o.x *= scale; o.y *= scale; o.z *= scale; o.w *= scale;
    __nv_bfloat16 h0 = __float2bfloat16(o.x);
    __nv_bfloat16 h1 = __float2bfloat16(o.y);
    __nv_bfloat16 h2 = __float2bfloat16(o.z);
    __nv_bfloat16 h3 = __float2bfloat16(o.w);
    __nv_bfloat162* hp = (__nv_bfloat162*)(hi + (size_t)idx * 4);
    __nv_bfloat162* lp = (__nv_bfloat162*)(lo + (size_t)idx * 4);
    hp[0] = __nv_bfloat162(h0, h1); hp[1] = __nv_bfloat162(h2, h3);
    lp[0] = __nv_bfloat162(__float2bfloat16(o.x - __bfloat162float(h0)),
                           __float2bfloat16(o.y - __bfloat162float(h1)));
    lp[1] = __nv_bfloat162(__float2bfloat16(o.z - __bfloat162float(h2)),
                           __float2bfloat16(o.w - __bfloat162float(h3)));
}

// ---------------------------------------------------------------------------
// V transpose + split: v[b][s][kvh][d] fp32 -> vht/vlt[b][kvh][d][S] bf16
// ---------------------------------------------------------------------------
__global__ void vsplitT_kernel(const float* __restrict__ v,
                               __nv_bfloat16* __restrict__ vh,
                               __nv_bfloat16* __restrict__ vl) {
    __shared__ float t[32][33];
    const int bkv = blockIdx.z;
    const int b = bkv / NKV, kvh = bkv % NKV;
    const int s0 = blockIdx.x * 32, d0 = blockIdx.y * 32;
    const int tx = threadIdx.x, ty = threadIdx.y;
#pragma unroll
    for (int j = 0; j < 32; j += 8) {
        int s = s0 + ty + j;
        t[ty + j][tx] = v[((size_t)(b * SEQ + s) * NKV + kvh) * HDIM + d0 + tx];
    }
    __syncthreads();
#pragma unroll
    for (int j = 0; j < 32; j += 8) {
        int d = d0 + ty + j;
        float val = t[tx][ty + j];
        __nv_bfloat16 h = __float2bfloat16(val);
        size_t o = ((size_t)(b * NKV + kvh) * HDIM + d) * SEQ + s0 + tx;
        vh[o] = h;
        vl[o] = __float2bfloat16(val - __bfloat162float(h));
    }
}

// ---------------------------------------------------------------------------
// Tensor-core GEMM: C = A @ W^T, 3-term bf16 split, ldmatrix + 1 sync/chunk.
// CTA 128x128, 8 warps (2m x 4n), BK=32, 2-stage cp.async.
// ---------------------------------------------------------------------------
#define LDS_STRIDE 40
#define ROWB (LDS_STRIDE * 2)                  // 80 bytes/row
#define ARR_BYTES  (128 * ROWB)                // 10240
#define STAGE_BYTES (4 * ARR_BYTES)            // 40960
#define GEMM_SMEM  (2 * STAGE_BYTES)           // 81920

__global__ __launch_bounds__(256)
void gemm_mma(const __nv_bfloat16* __restrict__ Ah, const __nv_bfloat16* __restrict__ Al,
              const __nv_bfloat16* __restrict__ Bh, const __nv_bfloat16* __restrict__ Bl,
              float* __restrict__ C, int M, int N, int K) {
    extern __shared__ char smem[];

    const int tid = threadIdx.x;
    const int wid = tid >> 5;
    const int lane = tid & 31;
    const int wm = (wid >> 2) * 64;
    const int wn = (wid & 3) * 32;
    const int lr = lane >> 2;
    const int lk = (lane & 3) * 2;

    const int bm = blockIdx.y * 128;
    const int bn = blockIdx.x * 128;

    const int l_row0 = tid >> 2;
    const int l_cw   = (tid & 3) * 8;

    const uint32_t smbase = smem_u32(smem);
    const uint32_t laneoff = (lane & 15) * ROWB + (lane >> 4) * 16;

    auto prefetch = [&](int s, int k0) {
        const __nv_bfloat16* gsrc[4] = {Ah, Al, Bh, Bl};
        char* st0 = smem + s * STAGE_BYTES;
#pragma unroll
        for (int t = 0; t < 4; t++) {
            const int rb = (t < 2) ? bm : bn;
            char* base = st0 + t * ARR_BYTES;
#pragma unroll
            for (int u = 0; u < 2; u++) {
                int row = l_row0 + u * 64;
                cp_async16(base + row * ROWB + l_cw * 2,
                           gsrc[t] + (size_t)(rb + row) * K + k0 + l_cw);
            }
        }
        CP_COMMIT();
    };

    float acc[4][4][4];
#pragma unroll
    for (int mi = 0; mi < 4; mi++)
#pragma unroll
        for (int ni = 0; ni < 4; ni++)
#pragma unroll
            for (int r = 0; r < 4; r++) acc[mi][ni][r] = 0.f;

    const int nchunk = K / 32;
    prefetch(0, 0);

    for (int ch = 0; ch < nchunk; ch++) {
        const int s = ch & 1;
        CP_WAIT(0);
        __syncthreads();
        if (ch + 1 < nchunk) prefetch(s ^ 1, (ch + 1) * 32);

        const uint32_t st0 = smbase + s * STAGE_BYTES;
        const uint32_t pAh = st0 + 0 * ARR_BYTES + wm * ROWB + laneoff;
        const uint32_t pAl = st0 + 1 * ARR_BYTES + wm * ROWB + laneoff;
        const uint32_t pBh = st0 + 2 * ARR_BYTES + wn * ROWB + laneoff;
        const uint32_t pBl = st0 + 3 * ARR_BYTES + wn * ROWB + laneoff;

#pragma unroll
        for (int kk = 0; kk < 2; kk++) {
            const uint32_t k0b = kk * 32;
            uint32_t Bh01[4], Bh23[4], Bl01[4], Bl23[4];
            ldmx4(Bh01, pBh + k0b);
            ldmx4(Bh23, pBh + 16 * ROWB + k0b);
            ldmx4(Bl01, pBl + k0b);
            ldmx4(Bl23, pBl + 16 * ROWB + k0b);
#pragma unroll
            for (int mi = 0; mi < 4; mi++) {
                uint32_t A_h[4], A_l[4];
                ldmx4(A_h, pAh + mi * 16 * ROWB + k0b);
                ldmx4(A_l, pAl + mi * 16 * ROWB + k0b);
                mma_bf16(acc[mi][0], A_h, Bh01[0], Bh01[2]);
                mma_bf16(acc[mi][0], A_h, Bl01[0], Bl01[2]);
                mma_bf16(acc[mi][0], A_l, Bh01[0], Bh01[2]);
                mma_bf16(acc[mi][1], A_h, Bh01[1], Bh01[3]);
                mma_bf16(acc[mi][1], A_h, Bl01[1], Bl01[3]);
                mma_bf16(acc[mi][1], A_l, Bh01[1], Bh01[3]);
                mma_bf16(acc[mi][2], A_h, Bh23[0], Bh23[2]);
                mma_bf16(acc[mi][2], A_h, Bl23[0], Bl23[2]);
                mma_bf16(acc[mi][2], A_l, Bh23[0], Bh23[2]);
                mma_bf16(acc[mi][3], A_h, Bh23[1], Bh23[3]);
                mma_bf16(acc[mi][3], A_h, Bl23[1], Bl23[3]);
                mma_bf16(acc[mi][3], A_l, Bh23[1], Bh23[3]);
            }
        }
        __syncthreads();
    }

#pragma unroll
    for (int mi = 0; mi < 4; mi++) {
        int row = bm + wm + mi * 16 + lr;
#pragma unroll
        for (int ni = 0; ni < 4; ni++) {
            int col = bn + wn + ni * 8 + lk;
            *(float2*)(C + (size_t)row * N + col) =
                make_float2(acc[mi][ni][0], acc[mi][ni][1]);
            *(float2*)(C + (size_t)(row + 8) * N + col) =
                make_float2(acc[mi][ni][2], acc[mi][ni][3]);
        }
    }
}

// ---------------------------------------------------------------------------
// Tensor-core flash attention (causal, GQA), bf16 3-term splits, ldmatrix.
// Grid (32, 64). 256 threads, 8 warps 2m x 4n. Tile 64 q x 64 keys.
// ---------------------------------------------------------------------------
#define KSTR  72
#define KROWB (KSTR * 2)   // 144 bytes
#define SSTRF 66
#define NEGBIG (-1e30f)
#define FLASH_SMEM (8 * 64 * KSTR * 2 + 64 * SSTRF * 4 + 3 * 64 * 4)

__global__ __launch_bounds__(256)
void flash_tc(const __nv_bfloat16* __restrict__ qh, const __nv_bfloat16* __restrict__ ql,
              const __nv_bfloat16* __restrict__ kh, const __nv_bfloat16* __restrict__ kl,
              const __nv_bfloat16* __restrict__ vht, const __nv_bfloat16* __restrict__ vlt,
              __nv_bfloat16* __restrict__ oh, __nv_bfloat16* __restrict__ ol) {
    extern __shared__ char smc[];
    __nv_bfloat16* sQh = (__nv_bfloat16*)smc;
    __nv_bfloat16* sQl = sQh + 64 * KSTR;
    __nv_bfloat16* sKh = sQl + 64 * KSTR;
    __nv_bfloat16* sKl = sKh + 64 * KSTR;
    __nv_bfloat16* sVh = sKl + 64 * KSTR;
    __nv_bfloat16* sVl = sVh + 64 * KSTR;
    __nv_bfloat16* sPh = sVl + 64 * KSTR;
    __nv_bfloat16* sPl = sPh + 64 * KSTR;
    float* sS    = (float*)(sPl + 64 * KSTR);
    float* row_m = sS + 64 * SSTRF;
    float* row_l = row_m + 64;
    float* row_a = row_l + 64;

    const int tid  = threadIdx.x;
    const int wid  = tid >> 5;
    const int lane = tid & 31;
    const int wm = (wid >> 2) * 32;
    const int wn = (wid & 3) * 16;
    const int lr = lane >> 2;
    const int lk = (lane & 3) * 2;

    const int qt  = gridDim.x - 1 - blockIdx.x;
    const int bh  = blockIdx.y;
    const int b   = bh >> 5;
    const int h   = bh & 31;
    const int kvh = h >> 2;

    const uint32_t uQh = smem_u32(sQh), uQl = smem_u32(sQl);
    const uint32_t uKh = smem_u32(sKh), uKl = smem_u32(sKl);
    const uint32_t uVh = smem_u32(sVh), uVl = smem_u32(sVl);
    const uint32_t uPh = smem_u32(sPh), uPl = smem_u32(sPl);
    const uint32_t laneoff = (lane & 15) * KROWB + (lane >> 4) * 16;

    // Q tile load (once)
#pragma unroll
    for (int u = 0; u < 2; u++) {
        int slot = tid + 256 * u;
        int row = slot >> 3, cw = slot & 7;
        const size_t go = ((size_t)(b * SEQ + qt * 64 + row) * NHEAD + h) * HDIM + cw * 8;
        cp_async16(sQh + row * KSTR + cw * 8, qh + go);
        cp_async16(sQl + row * KSTR + cw * 8, ql + go);
    }
    CP_COMMIT();

    if (tid < 64) { row_m[tid] = NEGBIG; row_l[tid] = 0.f; }

    float oacc[2][2][4];
#pragma unroll
    for (int mi = 0; mi < 2; mi++)
#pragma unroll
        for (int ni = 0; ni < 2; ni++)
#pragma unroll
            for (int r = 0; r < 4; r++) oacc[mi][ni][r] = 0.f;

    for (int kt = 0; kt <= qt; kt++) {
        // K loads (group), then V loads (group)
#pragma unroll
        for (int u = 0; u < 2; u++) {
            int slot = tid + 256 * u;
            int row = slot >> 3, cw = slot & 7;
            const size_t gk = ((size_t)(b * SEQ + kt * 64 + row) * NKV + kvh) * HDIM + cw * 8;
            cp_async16(sKh + row * KSTR + cw * 8, kh + gk);
            cp_async16(sKl + row * KSTR + cw * 8, kl + gk);
        }
        CP_COMMIT();
#pragma unroll
        for (int u = 0; u < 2; u++) {
            int slot = tid + 256 * u;
            int row = slot >> 3, cw = slot & 7;
            const size_t gv = ((size_t)(b * NKV + kvh) * HDIM + row) * SEQ + kt * 64 + cw * 8;
            cp_async16(sVh + row * KSTR + cw * 8, vht + gv);
            cp_async16(sVl + row * KSTR + cw * 8, vlt + gv);
        }
        CP_COMMIT();

        CP_WAIT(1);          // K (and Q) ready; V may still be in flight
        __syncthreads();

        // ---- S = Q @ K^T ----
        float sacc[2][2][4];
#pragma unroll
        for (int mi = 0; mi < 2; mi++)
#pragma unroll
            for (int ni = 0; ni < 2; ni++)
#pragma unroll
                for (int r = 0; r < 4; r++) sacc[mi][ni][r] = 0.f;

#pragma unroll
        for (int kk = 0; kk < 4; kk++) {
            const uint32_t k0b = kk * 32;
            uint32_t Kh4[4], Kl4[4];
            ldmx4(Kh4, uKh + wn * KROWB + laneoff + k0b);
            ldmx4(Kl4, uKl + wn * KROWB + laneoff + k0b);
#pragma unroll
            for (int mi = 0; mi < 2; mi++) {
                uint32_t Qh4[4], Ql4[4];
                ldmx4(Qh4, uQh + (wm + mi * 16) * KROWB + laneoff + k0b);
                ldmx4(Ql4, uQl + (wm + mi * 16) * KROWB + laneoff + k0b);
                mma_bf16(sacc[mi][0], Qh4, Kh4[0], Kh4[2]);
                mma_bf16(sacc[mi][0], Qh4, Kl4[0], Kl4[2]);
                mma_bf16(sacc[mi][0], Ql4, Kh4[0], Kh4[2]);
                mma_bf16(sacc[mi][1], Qh4, Kh4[1], Kh4[3]);
                mma_bf16(sacc[mi][1], Qh4, Kl4[1], Kl4[3]);
                mma_bf16(sacc[mi][1], Ql4, Kh4[1], Kh4[3]);
            }
        }

        // ---- mask + store scores ----
        const bool diag = (kt == qt);
#pragma unroll
        for (int mi = 0; mi < 2; mi++) {
#pragma unroll
            for (int ni = 0; ni < 2; ni++) {
                int r = wm + mi * 16 + lr;
                int c = wn + ni * 8 + lk;
                float s0 = sacc[mi][ni][0], s1 = sacc[mi][ni][1];
                float s2 = sacc[mi][ni][2], s3 = sacc[mi][ni][3];
                if (diag) {
                    if (c     > r)     s0 = NEGBIG;
                    if (c + 1 > r)     s1 = NEGBIG;
                    if (c     > r + 8) s2 = NEGBIG;
                    if (c + 1 > r + 8) s3 = NEGBIG;
                }
                *(float2*)&sS[r * SSTRF + c]       = make_float2(s0, s1);
                *(float2*)&sS[(r + 8) * SSTRF + c] = make_float2(s2, s3);
            }
        }
        __syncthreads();

        // ---- online softmax (4 threads/row) ----
        {
            const int row = tid >> 2, seg = tid & 3;
            const float* srow = sS + row * SSTRF + seg * 16;
            float mx = NEGBIG;
#pragma unroll
            for (int j = 0; j < 16; j++) mx = fmaxf(mx, srow[j]);
            mx = fmaxf(mx, __shfl_xor_sync(0xFFFFFFFF, mx, 1));
            mx = fmaxf(mx, __shfl_xor_sync(0xFFFFFFFF, mx, 2));
            const float mprev = row_m[row];
            const float mnew = fmaxf(mprev, mx);
            float sum = 0.f;
            __nv_bfloat16* ph = sPh + row * KSTR + seg * 16;
            __nv_bfloat16* pl = sPl + row * KSTR + seg * 16;
#pragma unroll
            for (int j = 0; j < 16; j++) {
                float p = __expf(srow[j] - mnew);
                sum += p;
                __nv_bfloat16 hp = __float2bfloat16(p);
                ph[j] = hp;
                pl[j] = __float2bfloat16(p - __bfloat162float(hp));
            }
            sum += __shfl_xor_sync(0xFFFFFFFF, sum, 1);
            sum += __shfl_xor_sync(0xFFFFFFFF, sum, 2);
            if (seg == 0) {
                float alpha = __expf(mprev - mnew);
                row_a[row] = alpha;
                row_l[row] = row_l[row] * alpha + sum;
                row_m[row] = mnew;
            }
        }
        CP_WAIT(0);          // V ready
        __syncthreads();

        // ---- rescale O, accumulate P @ V ----
#pragma unroll
        for (int mi = 0; mi < 2; mi++) {
            int r0 = wm + mi * 16 + lr;
            float a0 = row_a[r0], a1 = row_a[r0 + 8];
#pragma unroll
            for (int ni = 0; ni < 2; ni++) {
                oacc[mi][ni][0] *= a0; oacc[mi][ni][1] *= a0;
                oacc[mi][ni][2] *= a1; oacc[mi][ni][3] *= a1;
            }
        }
#pragma unroll
        for (int kk = 0; kk < 4; kk++) {
            const uint32_t k0b = kk * 32;
            uint32_t Vh4[4], Vl4[4];
            ldmx4(Vh4, uVh + wn * KROWB + laneoff + k0b);
            ldmx4(Vl4, uVl + wn * KROWB + laneoff + k0b);
#pragma unroll
            for (int mi = 0; mi < 2; mi++) {
                uint32_t Ph4[4], Pl4[4];
                ldmx4(Ph4, uPh + (wm + mi * 16) * KROWB + laneoff + k0b);
                ldmx4(Pl4, uPl + (wm + mi * 16) * KROWB + laneoff + k0b);
                mma_bf16(oacc[mi][0], Ph4, Vh4[0], Vh4[2]);
                mma_bf16(oacc[mi][0], Ph4, Vl4[0], Vl4[2]);
                mma_bf16(oacc[mi][0], Pl4, Vh4[0], Vh4[2]);
                mma_bf16(oacc[mi][1], Ph4, Vh4[1], Vh4[3]);
                mma_bf16(oacc[mi][1], Ph4, Vl4[1], Vl4[3]);
                mma_bf16(oacc[mi][1], Pl4, Vh4[1], Vh4[3]);
            }
        }
        __syncthreads();
    }

    // ---- normalize + write bf16 hi/lo output ----
#pragma unroll
    for (int mi = 0; mi < 2; mi++) {
        int r = wm + mi * 16 + lr;
        float inv0 = 1.f / row_l[r];
        float inv1 = 1.f / row_l[r + 8];
#pragma unroll
        for (int ni = 0; ni < 2; ni++) {
            int c = wn + ni * 8 + lk;
            size_t o0 = ((size_t)(b * SEQ + qt * 64 + r) * NHEAD + h) * HDIM + c;
            size_t o1 = ((size_t)(b * SEQ + qt * 64 + r + 8) * NHEAD + h) * HDIM + c;
            float v0 = oacc[mi][ni][0] * inv0, v1 = oacc[mi][ni][1] * inv0;
            float v2 = oacc[mi][ni][2] * inv1, v3 = oacc[mi][ni][3] * inv1;
            __nv_bfloat16 h0 = __float2bfloat16(v0), h1 = __float2bfloat16(v1);
            __nv_bfloat16 h2 = __float2bfloat16(v2), h3 = __float2bfloat16(v3);
            *(__nv_bfloat162*)(oh + o0) = __nv_bfloat162(h0, h1);
            *(__nv_bfloat162*)(oh + o1) = __nv_bfloat162(h2, h3);
            *(__nv_bfloat162*)(ol + o0) = __nv_bfloat162(
                __float2bfloat16(v0 - __bfloat162float(h0)),
                __float2bfloat16(v1 - __bfloat162float(h1)));
            *(__nv_bfloat162*)(ol + o1) = __nv_bfloat162(
                __float2bfloat16(v2 - __bfloat162float(h2)),
                __float2bfloat16(v3 - __bfloat162float(h3)));
        }
    }
}

// ---------------------------------------------------------------------------
// Host launcher
// ---------------------------------------------------------------------------
extern "C" void kernel_launch(void* const* d_in, const int* in_sizes, int n_in,
                              void* d_out, int out_size) {
    const float* hidden = (const float*)d_in[0];
    const float* cosb   = (const float*)d_in[1];
    const float* sinb   = (const float*)d_in[2];
    const float* Wq     = (const float*)d_in[4];
    const float* Wk     = (const float*)d_in[5];
    const float* Wv     = (const float*)d_in[6];
    const float* Wo     = (const float*)d_in[7];
    float* out = (float*)d_out;

    float *qp, *kp, *vp;
    cudaGetSymbolAddress((void**)&qp, g_q);
    cudaGetSymbolAddress((void**)&kp, g_k);
    cudaGetSymbolAddress((void**)&vp, g_v);

    __nv_bfloat16 *ah, *al, *oh, *ol, *wqh, *wql, *wkh, *wkl, *wvh, *wvl, *woh, *wol;
    __nv_bfloat16 *qhp, *qlp, *khp, *klp, *vhtp, *vltp;
    cudaGetSymbolAddress((void**)&ah, g_ah);   cudaGetSymbolAddress((void**)&al, g_al);
    cudaGetSymbolAddress((void**)&oh, g_oh);   cudaGetSymbolAddress((void**)&ol, g_ol);
    cudaGetSymbolAddress((void**)&wqh, g_wqh); cudaGetSymbolAddress((void**)&wql, g_wql);
    cudaGetSymbolAddress((void**)&wkh, g_wkh); cudaGetSymbolAddress((void**)&wkl, g_wkl);
    cudaGetSymbolAddress((void**)&wvh, g_wvh); cudaGetSymbolAddress((void**)&wvl, g_wvl);
    cudaGetSymbolAddress((void**)&woh, g_woh); cudaGetSymbolAddress((void**)&wol, g_wol);
    cudaGetSymbolAddress((void**)&qhp, g_qh);  cudaGetSymbolAddress((void**)&qlp, g_ql);
    cudaGetSymbolAddress((void**)&khp, g_kh);  cudaGetSymbolAddress((void**)&klp, g_kl);
    cudaGetSymbolAddress((void**)&vhtp, g_vht); cudaGetSymbolAddress((void**)&vltp, g_vlt);

    const int M = NBATCH * SEQ;  // 4096

    cudaFuncSetAttribute(gemm_mma, cudaFuncAttributeMaxDynamicSharedMemorySize,
                         GEMM_SMEM);
    cudaFuncSetAttribute(flash_tc, cudaFuncAttributeMaxDynamicSharedMemorySize,
                         FLASH_SMEM);

    // Launch order puts the big GEMMs at ncu's skip window (-s 5).
    int n4h = (M * HID) / 4;
    split_kernel<<<(n4h + 255) / 256, 256>>>(hidden, ah, al, n4h);          // 0
    int n4q = (2048 * 2048) / 4;
    split_kernel<<<(n4q + 255) / 256, 256>>>(Wq, wqh, wql, n4q);            // 1
    int n4k = (512 * 2048) / 4;
    split_kernel<<<(n4k + 255) / 256, 256>>>(Wk, wkh, wkl, n4k);            // 2
    split_kernel<<<(n4k + 255) / 256, 256>>>(Wv, wvh, wvl, n4k);            // 3

    gemm_mma<<<dim3(2048 / 128, M / 128), 256, GEMM_SMEM>>>(ah, al, wqh, wql, qp, M, 2048, 2048); // 4
    gemm_mma<<<dim3(512  / 128, M / 128), 256, GEMM_SMEM>>>(ah, al, wkh, wkl, kp, M, 512, 2048);  // 5
    gemm_mma<<<dim3(512  / 128, M / 128), 256, GEMM_SMEM>>>(ah, al, wvh, wvl, vp, M, 512, 2048);  // 6

    // Fused RoPE + scale + split
    int tq = M * NHEAD * 16;
    rope_split_kernel<<<(tq + 255) / 256, 256>>>(qp, cosb, sinb, qhp, qlp, NHEAD, tq, 0.125f); // 7
    int tk = M * NKV * 16;
    rope_split_kernel<<<(tk + 255) / 256, 256>>>(kp, cosb, sinb, khp, klp, NKV, tk, 1.f);      // 8

    vsplitT_kernel<<<dim3(SEQ / 32, HDIM / 32, NBATCH * NKV), dim3(32, 8)>>>(vp, vhtp, vltp);  // 9

    flash_tc<<<dim3(SEQ / 64, NBATCH * NHEAD), 256, FLASH_SMEM>>>(
        qhp, qlp, khp, klp, vhtp, vltp, oh, ol);                                               // 10

    split_kernel<<<(n4q + 255) / 256, 256>>>(Wo, woh, wol, n4q);                               // 11
    gemm_mma<<<dim3(2048 / 128, M / 128), 256, GEMM_SMEM>>>(oh, ol, woh, wol, out, M, 2048, 2048); // 12
}

// round 9
// speedup vs baseline: 1.0364x; 1.0364x over previous
#include <cuda_runtime.h>
#include <cuda_bf16.h>
#include <cstdint>
#include <math.h>

// Problem: B=2, S=2048, HID=2048, H=32, KVH=8, D=64, G=4, ROT=32
#define NBATCH 2
#define SEQ    2048
#define HID    2048
#define NHEAD  32
#define NKV    8
#define HDIM   64

// ---------------------------------------------------------------------------
// Scratch (device globals; no allocations allowed)
// ---------------------------------------------------------------------------
__device__ float g_v[NBATCH*SEQ*NKV*HDIM];

__device__ __nv_bfloat16 g_ah[4096*2048], g_al[4096*2048];     // hidden
__device__ __nv_bfloat16 g_oh[4096*2048], g_ol[4096*2048];     // attn out
__device__ __nv_bfloat16 g_wqh[2048*2048], g_wql[2048*2048];
__device__ __nv_bfloat16 g_wkh[512*2048],  g_wkl[512*2048];
__device__ __nv_bfloat16 g_wvh[512*2048],  g_wvl[512*2048];
__device__ __nv_bfloat16 g_woh[2048*2048], g_wol[2048*2048];
__device__ __nv_bfloat16 g_qh[NBATCH*SEQ*NHEAD*HDIM], g_ql[NBATCH*SEQ*NHEAD*HDIM];
__device__ __nv_bfloat16 g_kh[NBATCH*SEQ*NKV*HDIM],   g_kl[NBATCH*SEQ*NKV*HDIM];
__device__ __nv_bfloat16 g_vht[NBATCH*NKV*HDIM*SEQ],  g_vlt[NBATCH*NKV*HDIM*SEQ];

// ---------------------------------------------------------------------------
// helpers
// ---------------------------------------------------------------------------
__device__ __forceinline__ uint32_t smem_u32(const void* p) {
    uint32_t a;
    asm("{ .reg .u64 t; cvta.to.shared.u64 t, %1; cvt.u32.u64 %0, t; }"
        : "=r"(a) : "l"(p));
    return a;
}
__device__ __forceinline__ void mma_bf16(float* c, const uint32_t* a,
                                         uint32_t b0, uint32_t b1) {
    asm volatile(
        "mma.sync.aligned.m16n8k16.row.col.f32.bf16.bf16.f32 "
        "{%0,%1,%2,%3}, {%4,%5,%6,%7}, {%8,%9}, {%0,%1,%2,%3};"
        : "+f"(c[0]), "+f"(c[1]), "+f"(c[2]), "+f"(c[3])
        : "r"(a[0]), "r"(a[1]), "r"(a[2]), "r"(a[3]), "r"(b0), "r"(b1));
}
__device__ __forceinline__ void ldmx4(uint32_t* r, uint32_t saddr) {
    asm volatile("ldmatrix.sync.aligned.m8n8.x4.shared.b16 {%0,%1,%2,%3}, [%4];"
        : "=r"(r[0]), "=r"(r[1]), "=r"(r[2]), "=r"(r[3]) : "r"(saddr));
}
__device__ __forceinline__ void cp_async16(void* smem_dst, const void* gsrc) {
    uint32_t d;
    asm("{ .reg .u64 t; cvta.to.shared.u64 t, %1; cvt.u32.u64 %0, t; }"
        : "=r"(d) : "l"(smem_dst));
    asm volatile("cp.async.cg.shared.global [%0], [%1], 16;" :: "r"(d), "l"(gsrc));
}
#define CP_COMMIT() asm volatile("cp.async.commit_group;" ::: "memory")
#define CP_WAIT(n)  asm volatile("cp.async.wait_group %0;" :: "n"(n) : "memory")

// ---------------------------------------------------------------------------
// fp32 -> (bf16 hi, bf16 lo) split
// ---------------------------------------------------------------------------
__global__ void split_kernel(const float* __restrict__ x,
                             __nv_bfloat16* __restrict__ hi,
                             __nv_bfloat16* __restrict__ lo, int n4) {
    int i = blockIdx.x * blockDim.x + threadIdx.x;
    if (i >= n4) return;
    float4 v = ((const float4*)x)[i];
    __nv_bfloat16 h0 = __float2bfloat16(v.x);
    __nv_bfloat16 h1 = __float2bfloat16(v.y);
    __nv_bfloat16 h2 = __float2bfloat16(v.z);
    __nv_bfloat16 h3 = __float2bfloat16(v.w);
    __nv_bfloat162* hp = (__nv_bfloat162*)(hi + (size_t)i * 4);
    __nv_bfloat162* lp = (__nv_bfloat162*)(lo + (size_t)i * 4);
    hp[0] = __nv_bfloat162(h0, h1); hp[1] = __nv_bfloat162(h2, h3);
    lp[0] = __nv_bfloat162(__float2bfloat16(v.x - __bfloat162float(h0)),
                           __float2bfloat16(v.y - __bfloat162float(h1)));
    lp[1] = __nv_bfloat162(__float2bfloat16(v.z - __bfloat162float(h2)),
                           __float2bfloat16(v.w - __bfloat162float(h3)));
}

// ---------------------------------------------------------------------------
// V transpose + split: v[b][s][kvh][d] fp32 -> vht/vlt[b][kvh][d][S] bf16
// ---------------------------------------------------------------------------
__global__ void vsplitT_kernel(const float* __restrict__ v,
                               __nv_bfloat16* __restrict__ vh,
                               __nv_bfloat16* __restrict__ vl) {
    __shared__ float t[32][33];
    const int bkv = blockIdx.z;
    const int b = bkv / NKV, kvh = bkv % NKV;
    const int s0 = blockIdx.x * 32, d0 = blockIdx.y * 32;
    const int tx = threadIdx.x, ty = threadIdx.y;
#pragma unroll
    for (int j = 0; j < 32; j += 8) {
        int s = s0 + ty + j;
        t[ty + j][tx] = v[((size_t)(b * SEQ + s) * NKV + kvh) * HDIM + d0 + tx];
    }
    __syncthreads();
#pragma unroll
    for (int j = 0; j < 32; j += 8) {
        int d = d0 + ty + j;
        float val = t[tx][ty + j];
        __nv_bfloat16 h = __float2bfloat16(val);
        size_t o = ((size_t)(b * NKV + kvh) * HDIM + d) * SEQ + s0 + tx;
        vh[o] = h;
        vl[o] = __float2bfloat16(val - __bfloat162float(h));
    }
}

// ---------------------------------------------------------------------------
// Tensor-core GEMM: C = A @ W^T, 3-term bf16 split.
// CTA 128x128, 8 warps (2m x 4n), BK=32, 2-stage cp.async (R5 pipeline order),
// ldmatrix fragment loads (R6 core, proven correct).
// MODE 0: write fp32 C. MODE 2: rope(first 32 dims of each 64-dim head) +
//         scale + bf16 hi/lo split written directly.
// ---------------------------------------------------------------------------
#define LDS_STRIDE 40
#define ROWB (LDS_STRIDE * 2)                  // 80 bytes/row
#define ARR_BYTES  (128 * ROWB)
#define STAGE_BYTES (4 * ARR_BYTES)
#define GEMM_SMEM  (2 * STAGE_BYTES)           // 81920

template<int MODE>
__global__ __launch_bounds__(256)
void gemm_mma(const __nv_bfloat16* __restrict__ Ah, const __nv_bfloat16* __restrict__ Al,
              const __nv_bfloat16* __restrict__ Bh, const __nv_bfloat16* __restrict__ Bl,
              float* __restrict__ Cf,
              __nv_bfloat16* __restrict__ Ch, __nv_bfloat16* __restrict__ Cl,
              const float* __restrict__ ct, const float* __restrict__ st,
              float scale, int M, int N, int K) {
    extern __shared__ char smem[];

    const int tid = threadIdx.x;
    const int wid = tid >> 5;
    const int lane = tid & 31;
    const int wm = (wid >> 2) * 64;
    const int wn = (wid & 3) * 32;
    const int lr = lane >> 2;
    const int lk = (lane & 3) * 2;

    const int bm = blockIdx.y * 128;
    const int bn = blockIdx.x * 128;

    const int l_row0 = tid >> 2;
    const int l_cw   = (tid & 3) * 8;

    const uint32_t smbase = smem_u32(smem);
    const uint32_t laneoff = (lane & 15) * ROWB + (lane >> 4) * 16;

    auto prefetch = [&](int s, int k0) {
        const __nv_bfloat16* gsrc[4] = {Ah, Al, Bh, Bl};
        char* st0 = smem + s * STAGE_BYTES;
#pragma unroll
        for (int t = 0; t < 4; t++) {
            const int rb = (t < 2) ? bm : bn;
            char* base = st0 + t * ARR_BYTES;
#pragma unroll
            for (int u = 0; u < 2; u++) {
                int row = l_row0 + u * 64;
                cp_async16(base + row * ROWB + l_cw * 2,
                           gsrc[t] + (size_t)(rb + row) * K + k0 + l_cw);
            }
        }
        CP_COMMIT();
    };

    float acc[4][4][4];
#pragma unroll
    for (int mi = 0; mi < 4; mi++)
#pragma unroll
        for (int ni = 0; ni < 4; ni++)
#pragma unroll
            for (int r = 0; r < 4; r++) acc[mi][ni][r] = 0.f;

    const int nchunk = K / 32;
    prefetch(0, 0);

    for (int ch = 0; ch < nchunk; ch++) {
        const int s = ch & 1;
        // R5 pipeline order: issue next-chunk loads BEFORE waiting on current.
        if (ch + 1 < nchunk) {
            prefetch(s ^ 1, (ch + 1) * 32);
            CP_WAIT(1);
        } else {
            CP_WAIT(0);
        }
        __syncthreads();

        const uint32_t st0 = smbase + s * STAGE_BYTES;
        const uint32_t pAh = st0 + 0 * ARR_BYTES + wm * ROWB + laneoff;
        const uint32_t pAl = st0 + 1 * ARR_BYTES + wm * ROWB + laneoff;
        const uint32_t pBh = st0 + 2 * ARR_BYTES + wn * ROWB + laneoff;
        const uint32_t pBl = st0 + 3 * ARR_BYTES + wn * ROWB + laneoff;

#pragma unroll
        for (int kk = 0; kk < 2; kk++) {
            const uint32_t k0b = kk * 32;
            uint32_t Bh01[4], Bh23[4], Bl01[4], Bl23[4];
            ldmx4(Bh01, pBh + k0b);
            ldmx4(Bh23, pBh + 16 * ROWB + k0b);
            ldmx4(Bl01, pBl + k0b);
            ldmx4(Bl23, pBl + 16 * ROWB + k0b);
#pragma unroll
            for (int mi = 0; mi < 4; mi++) {
                uint32_t A_h[4], A_l[4];
                ldmx4(A_h, pAh + mi * 16 * ROWB + k0b);
                ldmx4(A_l, pAl + mi * 16 * ROWB + k0b);
                mma_bf16(acc[mi][0], A_h, Bh01[0], Bh01[2]);
                mma_bf16(acc[mi][0], A_h, Bl01[0], Bl01[2]);
                mma_bf16(acc[mi][0], A_l, Bh01[0], Bh01[2]);
                mma_bf16(acc[mi][1], A_h, Bh01[1], Bh01[3]);
                mma_bf16(acc[mi][1], A_h, Bl01[1], Bl01[3]);
                mma_bf16(acc[mi][1], A_l, Bh01[1], Bh01[3]);
                mma_bf16(acc[mi][2], A_h, Bh23[0], Bh23[2]);
                mma_bf16(acc[mi][2], A_h, Bl23[0], Bl23[2]);
                mma_bf16(acc[mi][2], A_l, Bh23[0], Bh23[2]);
                mma_bf16(acc[mi][3], A_h, Bh23[1], Bh23[3]);
                mma_bf16(acc[mi][3], A_h, Bl23[1], Bl23[3]);
                mma_bf16(acc[mi][3], A_l, Bh23[1], Bh23[3]);
            }
        }
        __syncthreads();
    }

    if (MODE == 0) {
#pragma unroll
        for (int mi = 0; mi < 4; mi++) {
            int row = bm + wm + mi * 16 + lr;
#pragma unroll
            for (int ni = 0; ni < 4; ni++) {
                int col = bn + wn + ni * 8 + lk;
                *(float2*)(Cf + (size_t)row * N + col) =
                    make_float2(acc[mi][ni][0], acc[mi][ni][1]);
                *(float2*)(Cf + (size_t)(row + 8) * N + col) =
                    make_float2(acc[mi][ni][2], acc[mi][ni][3]);
            }
        }
    } else {
        // MODE 2: partial RoPE (cols with (c&63) < 32), scale, hi/lo split.
        // Register pairing: (ni, ni+2) hold cols c and c+16 in the same thread.
        const bool lower = (((bn + wn) & 63) == 0);
        if (lower) {
#pragma unroll
            for (int mi = 0; mi < 4; mi++) {
                int r0 = bm + wm + mi * 16 + lr;
#pragma unroll
                for (int nj = 0; nj < 2; nj++) {
                    int dlo = nj * 8 + lk;                 // 0..14, within [0,16)
                    float2 c0 = *(const float2*)(ct + (size_t)r0 * 32 + dlo);
                    float2 s0 = *(const float2*)(st + (size_t)r0 * 32 + dlo);
                    float2 c1 = *(const float2*)(ct + (size_t)(r0 + 8) * 32 + dlo);
                    float2 s1 = *(const float2*)(st + (size_t)(r0 + 8) * 32 + dlo);
                    float* plo = acc[mi][nj];
                    float* phi = acc[mi][nj + 2];
                    float xl, xh;
                    xl = plo[0]; xh = phi[0];
                    plo[0] = xl * c0.x - xh * s0.x; phi[0] = xh * c0.x + xl * s0.x;
                    xl = plo[1]; xh = phi[1];
                    plo[1] = xl * c0.y - xh * s0.y; phi[1] = xh * c0.y + xl * s0.y;
                    xl = plo[2]; xh = phi[2];
                    plo[2] = xl * c1.x - xh * s1.x; phi[2] = xh * c1.x + xl * s1.x;
                    xl = plo[3]; xh = phi[3];
                    plo[3] = xl * c1.y - xh * s1.y; phi[3] = xh * c1.y + xl * s1.y;
                }
            }
        }
#pragma unroll
        for (int mi = 0; mi < 4; mi++) {
            int row = bm + wm + mi * 16 + lr;
#pragma unroll
            for (int ni = 0; ni < 4; ni++) {
                int col = bn + wn + ni * 8 + lk;
                float v0 = acc[mi][ni][0] * scale, v1 = acc[mi][ni][1] * scale;
                float v2 = acc[mi][ni][2] * scale, v3 = acc[mi][ni][3] * scale;
                __nv_bfloat16 h0 = __float2bfloat16(v0), h1 = __float2bfloat16(v1);
                __nv_bfloat16 h2 = __float2bfloat16(v2), h3 = __float2bfloat16(v3);
                size_t o0 = (size_t)row * N + col;
                size_t o1 = (size_t)(row + 8) * N + col;
                *(__nv_bfloat162*)(Ch + o0) = __nv_bfloat162(h0, h1);
                *(__nv_bfloat162*)(Ch + o1) = __nv_bfloat162(h2, h3);
                *(__nv_bfloat162*)(Cl + o0) = __nv_bfloat162(
                    __float2bfloat16(v0 - __bfloat162float(h0)),
                    __float2bfloat16(v1 - __bfloat162float(h1)));
                *(__nv_bfloat162*)(Cl + o1) = __nv_bfloat162(
                    __float2bfloat16(v2 - __bfloat162float(h2)),
                    __float2bfloat16(v3 - __bfloat162float(h3)));
            }
        }
    }
}

// ---------------------------------------------------------------------------
// Tensor-core flash attention — EXACT R5 version (known 1546us config).
// ---------------------------------------------------------------------------
#define KSTR  72
#define SSTRF 66
#define NEGBIG (-1e30f)
#define FLASH_SMEM (8 * 64 * KSTR * 2 + 64 * SSTRF * 4 + 3 * 64 * 4)

__global__ __launch_bounds__(256)
void flash_tc(const __nv_bfloat16* __restrict__ qh, const __nv_bfloat16* __restrict__ ql,
              const __nv_bfloat16* __restrict__ kh, const __nv_bfloat16* __restrict__ kl,
              const __nv_bfloat16* __restrict__ vht, const __nv_bfloat16* __restrict__ vlt,
              __nv_bfloat16* __restrict__ oh, __nv_bfloat16* __restrict__ ol) {
    extern __shared__ char smc[];
    __nv_bfloat16* sQh = (__nv_bfloat16*)smc;
    __nv_bfloat16* sQl = sQh + 64 * KSTR;
    __nv_bfloat16* sKh = sQl + 64 * KSTR;
    __nv_bfloat16* sKl = sKh + 64 * KSTR;
    __nv_bfloat16* sVh = sKl + 64 * KSTR;
    __nv_bfloat16* sVl = sVh + 64 * KSTR;
    __nv_bfloat16* sPh = sVl + 64 * KSTR;
    __nv_bfloat16* sPl = sPh + 64 * KSTR;
    float* sS    = (float*)(sPl + 64 * KSTR);
    float* row_m = sS + 64 * SSTRF;
    float* row_l = row_m + 64;
    float* row_a = row_l + 64;

    const int tid  = threadIdx.x;
    const int wid  = tid >> 5;
    const int lane = tid & 31;
    const int wm = (wid >> 2) * 32;
    const int wn = (wid & 3) * 16;
    const int lr = lane >> 2;
    const int lk = (lane & 3) * 2;

    const int qt  = gridDim.x - 1 - blockIdx.x;
    const int bh  = blockIdx.y;
    const int b   = bh >> 5;
    const int h   = bh & 31;
    const int kvh = h >> 2;

#pragma unroll
    for (int u = 0; u < 2; u++) {
        int slot = tid + 256 * u;
        int row = slot >> 3, cw = slot & 7;
        const size_t go = ((size_t)(b * SEQ + qt * 64 + row) * NHEAD + h) * HDIM + cw * 8;
        cp_async16(sQh + row * KSTR + cw * 8, qh + go);
        cp_async16(sQl + row * KSTR + cw * 8, ql + go);
    }
    CP_COMMIT();

    if (tid < 64) { row_m[tid] = NEGBIG; row_l[tid] = 0.f; }

    float oacc[2][2][4];
#pragma unroll
    for (int mi = 0; mi < 2; mi++)
#pragma unroll
        for (int ni = 0; ni < 2; ni++)
#pragma unroll
            for (int r = 0; r < 4; r++) oacc[mi][ni][r] = 0.f;

    for (int kt = 0; kt <= qt; kt++) {
#pragma unroll
        for (int u = 0; u < 2; u++) {
            int slot = tid + 256 * u;
            int row = slot >> 3, cw = slot & 7;
            const size_t gk = ((size_t)(b * SEQ + kt * 64 + row) * NKV + kvh) * HDIM + cw * 8;
            cp_async16(sKh + row * KSTR + cw * 8, kh + gk);
            cp_async16(sKl + row * KSTR + cw * 8, kl + gk);
            const size_t gv = ((size_t)(b * NKV + kvh) * HDIM + row) * SEQ + kt * 64 + cw * 8;
            cp_async16(sVh + row * KSTR + cw * 8, vht + gv);
            cp_async16(sVl + row * KSTR + cw * 8, vlt + gv);
        }
        CP_COMMIT();
        CP_WAIT(0);
        __syncthreads();

        float sacc[2][2][4];
#pragma unroll
        for (int mi = 0; mi < 2; mi++)
#pragma unroll
            for (int ni = 0; ni < 2; ni++)
#pragma unroll
                for (int r = 0; r < 4; r++) sacc[mi][ni][r] = 0.f;

#pragma unroll
        for (int kk = 0; kk < 4; kk++) {
            const int k0 = kk * 16;
            uint32_t kbh[2][2], kbl[2][2];
#pragma unroll
            for (int ni = 0; ni < 2; ni++) {
                int n = wn + ni * 8 + lr;
                kbh[ni][0] = *(const uint32_t*)&sKh[n * KSTR + k0 + lk];
                kbh[ni][1] = *(const uint32_t*)&sKh[n * KSTR + k0 + lk + 8];
                kbl[ni][0] = *(const uint32_t*)&sKl[n * KSTR + k0 + lk];
                kbl[ni][1] = *(const uint32_t*)&sKl[n * KSTR + k0 + lk + 8];
            }
#pragma unroll
            for (int mi = 0; mi < 2; mi++) {
                int r0 = wm + mi * 16 + lr;
                uint32_t qah[4], qal[4];
                qah[0] = *(const uint32_t*)&sQh[(r0    ) * KSTR + k0 + lk];
                qah[1] = *(const uint32_t*)&sQh[(r0 + 8) * KSTR + k0 + lk];
                qah[2] = *(const uint32_t*)&sQh[(r0    ) * KSTR + k0 + lk + 8];
                qah[3] = *(const uint32_t*)&sQh[(r0 + 8) * KSTR + k0 + lk + 8];
                qal[0] = *(const uint32_t*)&sQl[(r0    ) * KSTR + k0 + lk];
                qal[1] = *(const uint32_t*)&sQl[(r0 + 8) * KSTR + k0 + lk];
                qal[2] = *(const uint32_t*)&sQl[(r0    ) * KSTR + k0 + lk + 8];
                qal[3] = *(const uint32_t*)&sQl[(r0 + 8) * KSTR + k0 + lk + 8];
#pragma unroll
                for (int ni = 0; ni < 2; ni++) {
                    mma_bf16(sacc[mi][ni], qah, kbh[ni][0], kbh[ni][1]);
                    mma_bf16(sacc[mi][ni], qah, kbl[ni][0], kbl[ni][1]);
                    mma_bf16(sacc[mi][ni], qal, kbh[ni][0], kbh[ni][1]);
                }
            }
        }

        const bool diag = (kt == qt);
#pragma unroll
        for (int mi = 0; mi < 2; mi++) {
#pragma unroll
            for (int ni = 0; ni < 2; ni++) {
                int r = wm + mi * 16 + lr;
                int c = wn + ni * 8 + lk;
                float s0 = sacc[mi][ni][0], s1 = sacc[mi][ni][1];
                float s2 = sacc[mi][ni][2], s3 = sacc[mi][ni][3];
                if (diag) {
                    if (c     > r)     s0 = NEGBIG;
                    if (c + 1 > r)     s1 = NEGBIG;
                    if (c     > r + 8) s2 = NEGBIG;
                    if (c + 1 > r + 8) s3 = NEGBIG;
                }
                *(float2*)&sS[r * SSTRF + c]       = make_float2(s0, s1);
                *(float2*)&sS[(r + 8) * SSTRF + c] = make_float2(s2, s3);
            }
        }
        __syncthreads();

        {
            const int row = tid >> 2, seg = tid & 3;
            const float* srow = sS + row * SSTRF + seg * 16;
            float mx = NEGBIG;
#pragma unroll
            for (int j = 0; j < 16; j++) mx = fmaxf(mx, srow[j]);
            mx = fmaxf(mx, __shfl_xor_sync(0xFFFFFFFF, mx, 1));
            mx = fmaxf(mx, __shfl_xor_sync(0xFFFFFFFF, mx, 2));
            const float mprev = row_m[row];
            const float mnew = fmaxf(mprev, mx);
            float sum = 0.f;
            __nv_bfloat16* ph = sPh + row * KSTR + seg * 16;
            __nv_bfloat16* pl = sPl + row * KSTR + seg * 16;
#pragma unroll
            for (int j = 0; j < 16; j++) {
                float p = __expf(srow[j] - mnew);
                sum += p;
                __nv_bfloat16 hp = __float2bfloat16(p);
                ph[j] = hp;
                pl[j] = __float2bfloat16(p - __bfloat162float(hp));
            }
            sum += __shfl_xor_sync(0xFFFFFFFF, sum, 1);
            sum += __shfl_xor_sync(0xFFFFFFFF, sum, 2);
            if (seg == 0) {
                float alpha = __expf(mprev - mnew);
                row_a[row] = alpha;
                row_l[row] = row_l[row] * alpha + sum;
                row_m[row] = mnew;
            }
        }
        __syncthreads();

#pragma unroll
        for (int mi = 0; mi < 2; mi++) {
            int r0 = wm + mi * 16 + lr;
            float a0 = row_a[r0], a1 = row_a[r0 + 8];
#pragma unroll
            for (int ni = 0; ni < 2; ni++) {
                oacc[mi][ni][0] *= a0; oacc[mi][ni][1] *= a0;
                oacc[mi][ni][2] *= a1; oacc[mi][ni][3] *= a1;
            }
        }
#pragma unroll
        for (int kk = 0; kk < 4; kk++) {
            const int k0 = kk * 16;
            uint32_t vbh[2][2], vbl[2][2];
#pragma unroll
            for (int ni = 0; ni < 2; ni++) {
                int n = wn + ni * 8 + lr;
                vbh[ni][0] = *(const uint32_t*)&sVh[n * KSTR + k0 + lk];
                vbh[ni][1] = *(const uint32_t*)&sVh[n * KSTR + k0 + lk + 8];
                vbl[ni][0] = *(const uint32_t*)&sVl[n * KSTR + k0 + lk];
                vbl[ni][1] = *(const uint32_t*)&sVl[n * KSTR + k0 + lk + 8];
            }
#pragma unroll
            for (int mi = 0; mi < 2; mi++) {
                int r0 = wm + mi * 16 + lr;
                uint32_t pah[4], pal[4];
                pah[0] = *(const uint32_t*)&sPh[(r0    ) * KSTR + k0 + lk];
                pah[1] = *(const uint32_t*)&sPh[(r0 + 8) * KSTR + k0 + lk];
                pah[2] = *(const uint32_t*)&sPh[(r0    ) * KSTR + k0 + lk + 8];
                pah[3] = *(const uint32_t*)&sPh[(r0 + 8) * KSTR + k0 + lk + 8];
                pal[0] = *(const uint32_t*)&sPl[(r0    ) * KSTR + k0 + lk];
                pal[1] = *(const uint32_t*)&sPl[(r0 + 8) * KSTR + k0 + lk];
                pal[2] = *(const uint32_t*)&sPl[(r0    ) * KSTR + k0 + lk + 8];
                pal[3] = *(const uint32_t*)&sPl[(r0 + 8) * KSTR + k0 + lk + 8];
#pragma unroll
                for (int ni = 0; ni < 2; ni++) {
                    mma_bf16(oacc[mi][ni], pah, vbh[ni][0], vbh[ni][1]);
                    mma_bf16(oacc[mi][ni], pah, vbl[ni][0], vbl[ni][1]);
                    mma_bf16(oacc[mi][ni], pal, vbh[ni][0], vbh[ni][1]);
                }
            }
        }
        __syncthreads();
    }

#pragma unroll
    for (int mi = 0; mi < 2; mi++) {
        int r = wm + mi * 16 + lr;
        float inv0 = 1.f / row_l[r];
        float inv1 = 1.f / row_l[r + 8];
#pragma unroll
        for (int ni = 0; ni < 2; ni++) {
            int c = wn + ni * 8 + lk;
            size_t o0 = ((size_t)(b * SEQ + qt * 64 + r) * NHEAD + h) * HDIM + c;
            size_t o1 = ((size_t)(b * SEQ + qt * 64 + r + 8) * NHEAD + h) * HDIM + c;
            float v0 = oacc[mi][ni][0] * inv0, v1 = oacc[mi][ni][1] * inv0;
            float v2 = oacc[mi][ni][2] * inv1, v3 = oacc[mi][ni][3] * inv1;
            __nv_bfloat16 h0 = __float2bfloat16(v0), h1 = __float2bfloat16(v1);
            __nv_bfloat16 h2 = __float2bfloat16(v2), h3 = __float2bfloat16(v3);
            *(__nv_bfloat162*)(oh + o0) = __nv_bfloat162(h0, h1);
            *(__nv_bfloat162*)(oh + o1) = __nv_bfloat162(h2, h3);
            *(__nv_bfloat162*)(ol + o0) = __nv_bfloat162(
                __float2bfloat16(v0 - __bfloat162float(h0)),
                __float2bfloat16(v1 - __bfloat162float(h1)));
            *(__nv_bfloat162*)(ol + o1) = __nv_bfloat162(
                __float2bfloat16(v2 - __bfloat162float(h2)),
                __float2bfloat16(v3 - __bfloat162float(h3)));
        }
    }
}

// ---------------------------------------------------------------------------
// Host launcher
// ---------------------------------------------------------------------------
extern "C" void kernel_launch(void* const* d_in, const int* in_sizes, int n_in,
                              void* d_out, int out_size) {
    const float* hidden = (const float*)d_in[0];
    const float* cosb   = (const float*)d_in[1];
    const float* sinb   = (const float*)d_in[2];
    const float* Wq     = (const float*)d_in[4];
    const float* Wk     = (const float*)d_in[5];
    const float* Wv     = (const float*)d_in[6];
    const float* Wo     = (const float*)d_in[7];
    float* out = (float*)d_out;

    float* vp;
    cudaGetSymbolAddress((void**)&vp, g_v);

    __nv_bfloat16 *ah, *al, *oh, *ol, *wqh, *wql, *wkh, *wkl, *wvh, *wvl, *woh, *wol;
    __nv_bfloat16 *qhp, *qlp, *khp, *klp, *vhtp, *vltp;
    cudaGetSymbolAddress((void**)&ah, g_ah);   cudaGetSymbolAddress((void**)&al, g_al);
    cudaGetSymbolAddress((void**)&oh, g_oh);   cudaGetSymbolAddress((void**)&ol, g_ol);
    cudaGetSymbolAddress((void**)&wqh, g_wqh); cudaGetSymbolAddress((void**)&wql, g_wql);
    cudaGetSymbolAddress((void**)&wkh, g_wkh); cudaGetSymbolAddress((void**)&wkl, g_wkl);
    cudaGetSymbolAddress((void**)&wvh, g_wvh); cudaGetSymbolAddress((void**)&wvl, g_wvl);
    cudaGetSymbolAddress((void**)&woh, g_woh); cudaGetSymbolAddress((void**)&wol, g_wol);
    cudaGetSymbolAddress((void**)&qhp, g_qh);  cudaGetSymbolAddress((void**)&qlp, g_ql);
    cudaGetSymbolAddress((void**)&khp, g_kh);  cudaGetSymbolAddress((void**)&klp, g_kl);
    cudaGetSymbolAddress((void**)&vhtp, g_vht); cudaGetSymbolAddress((void**)&vltp, g_vlt);

    const int M = NBATCH * SEQ;  // 4096

    cudaFuncSetAttribute(gemm_mma<0>, cudaFuncAttributeMaxDynamicSharedMemorySize,
                         GEMM_SMEM);
    cudaFuncSetAttribute(gemm_mma<2>, cudaFuncAttributeMaxDynamicSharedMemorySize,
                         GEMM_SMEM);
    cudaFuncSetAttribute(flash_tc, cudaFuncAttributeMaxDynamicSharedMemorySize,
                         FLASH_SMEM);

    // input splits
    int n4h = (M * HID) / 4;
    split_kernel<<<(n4h + 255) / 256, 256>>>(hidden, ah, al, n4h);
    int n4q = (2048 * 2048) / 4;
    split_kernel<<<(n4q + 255) / 256, 256>>>(Wq, wqh, wql, n4q);
    int n4k = (512 * 2048) / 4;
    split_kernel<<<(n4k + 255) / 256, 256>>>(Wk, wkh, wkl, n4k);
    split_kernel<<<(n4k + 255) / 256, 256>>>(Wv, wvh, wvl, n4k);
    split_kernel<<<(n4q + 255) / 256, 256>>>(Wo, woh, wol, n4q);

    // Q projection + fused rope + scale + split  (launch #5 for ncu -s 5)
    gemm_mma<2><<<dim3(2048 / 128, M / 128), 256, GEMM_SMEM>>>(
        ah, al, wqh, wql, nullptr, qhp, qlp, cosb, sinb, 0.125f, M, 2048, 2048);
    // K projection + fused rope + split
    gemm_mma<2><<<dim3(512 / 128, M / 128), 256, GEMM_SMEM>>>(
        ah, al, wkh, wkl, nullptr, khp, klp, cosb, sinb, 1.f, M, 512, 2048);
    // V projection (fp32 out, transposed+split next)
    gemm_mma<0><<<dim3(512 / 128, M / 128), 256, GEMM_SMEM>>>(
        ah, al, wvh, wvl, vp, nullptr, nullptr, nullptr, nullptr, 1.f, M, 512, 2048);

    vsplitT_kernel<<<dim3(SEQ / 32, HDIM / 32, NBATCH * NKV), dim3(32, 8)>>>(vp, vhtp, vltp);

    flash_tc<<<dim3(SEQ / 64, NBATCH * NHEAD), 256, FLASH_SMEM>>>(
        qhp, qlp, khp, klp, vhtp, vltp, oh, ol);

    // Output projection
    gemm_mma<0><<<dim3(2048 / 128, M / 128), 256, GEMM_SMEM>>>(
        oh, ol, woh, wol, out, nullptr, nullptr, nullptr, nullptr, 1.f, M, 2048, 2048);
}

// round 10
// speedup vs baseline: 1.2793x; 1.2343x over previous
#include <cuda_runtime.h>
#include <cuda_bf16.h>
#include <cuda_fp16.h>
#include <cstdint>
#include <math.h>

// Problem: B=2, S=2048, HID=2048, H=32, KVH=8, D=64, G=4, ROT=32
#define NBATCH 2
#define SEQ    2048
#define HID    2048
#define NHEAD  32
#define NKV    8
#define HDIM   64

// ---------------------------------------------------------------------------
// Scratch (device globals; no allocations allowed)
// ---------------------------------------------------------------------------
__device__ float g_q[NBATCH*SEQ*NHEAD*HDIM];
__device__ float g_k[NBATCH*SEQ*NKV*HDIM];
__device__ float g_v[NBATCH*SEQ*NKV*HDIM];

__device__ __nv_bfloat16 g_ah[4096*2048], g_al[4096*2048];     // hidden
__device__ __nv_bfloat16 g_oh[4096*2048], g_ol[4096*2048];     // attn out
__device__ __nv_bfloat16 g_wqh[2048*2048], g_wql[2048*2048];
__device__ __nv_bfloat16 g_wkh[512*2048],  g_wkl[512*2048];
__device__ __nv_bfloat16 g_wvh[512*2048],  g_wvl[512*2048];
__device__ __nv_bfloat16 g_woh[2048*2048], g_wol[2048*2048];
// fp16 attention operands
__device__ __half g_qh[NBATCH*SEQ*NHEAD*HDIM];
__device__ __half g_kh[NBATCH*SEQ*NKV*HDIM];
__device__ __half g_vht[NBATCH*NKV*HDIM*SEQ];   // [b][kvh][d][S]

// ---------------------------------------------------------------------------
// helpers
// ---------------------------------------------------------------------------
__device__ __forceinline__ void mma_bf16(float* c, const uint32_t* a,
                                         uint32_t b0, uint32_t b1) {
    asm volatile(
        "mma.sync.aligned.m16n8k16.row.col.f32.bf16.bf16.f32 "
        "{%0,%1,%2,%3}, {%4,%5,%6,%7}, {%8,%9}, {%0,%1,%2,%3};"
        : "+f"(c[0]), "+f"(c[1]), "+f"(c[2]), "+f"(c[3])
        : "r"(a[0]), "r"(a[1]), "r"(a[2]), "r"(a[3]), "r"(b0), "r"(b1));
}
__device__ __forceinline__ void mma_f16(float* c, const uint32_t* a,
                                        uint32_t b0, uint32_t b1) {
    asm volatile(
        "mma.sync.aligned.m16n8k16.row.col.f32.f16.f16.f32 "
        "{%0,%1,%2,%3}, {%4,%5,%6,%7}, {%8,%9}, {%0,%1,%2,%3};"
        : "+f"(c[0]), "+f"(c[1]), "+f"(c[2]), "+f"(c[3])
        : "r"(a[0]), "r"(a[1]), "r"(a[2]), "r"(a[3]), "r"(b0), "r"(b1));
}
__device__ __forceinline__ void cp_async16(void* smem_dst, const void* gsrc) {
    uint32_t d;
    asm("{ .reg .u64 t; cvta.to.shared.u64 t, %1; cvt.u32.u64 %0, t; }"
        : "=r"(d) : "l"(smem_dst));
    asm volatile("cp.async.cg.shared.global [%0], [%1], 16;" :: "r"(d), "l"(gsrc));
}
#define CP_COMMIT() asm volatile("cp.async.commit_group;" ::: "memory")
#define CP_WAIT(n)  asm volatile("cp.async.wait_group %0;" :: "n"(n) : "memory")

// ---------------------------------------------------------------------------
// fp32 -> (bf16 hi, bf16 lo) split, vectorized x4
// ---------------------------------------------------------------------------
__global__ void split_kernel(const float* __restrict__ x,
                             __nv_bfloat16* __restrict__ hi,
                             __nv_bfloat16* __restrict__ lo, int n4) {
    int i = blockIdx.x * blockDim.x + threadIdx.x;
    if (i >= n4) return;
    float4 v = ((const float4*)x)[i];
    __nv_bfloat16 h0 = __float2bfloat16(v.x);
    __nv_bfloat16 h1 = __float2bfloat16(v.y);
    __nv_bfloat16 h2 = __float2bfloat16(v.z);
    __nv_bfloat16 h3 = __float2bfloat16(v.w);
    __nv_bfloat162* hp = (__nv_bfloat162*)(hi + (size_t)i * 4);
    __nv_bfloat162* lp = (__nv_bfloat162*)(lo + (size_t)i * 4);
    hp[0] = __nv_bfloat162(h0, h1); hp[1] = __nv_bfloat162(h2, h3);
    lp[0] = __nv_bfloat162(__float2bfloat16(v.x - __bfloat162float(h0)),
                           __float2bfloat16(v.y - __bfloat162float(h1)));
    lp[1] = __nv_bfloat162(__float2bfloat16(v.z - __bfloat162float(h2)),
                           __float2bfloat16(v.w - __bfloat162float(h3)));
}

// ---------------------------------------------------------------------------
// fp32 -> fp16 with scale, vectorized x4
// ---------------------------------------------------------------------------
__global__ void tohalf_kernel(const float* __restrict__ x,
                              __half* __restrict__ y, int n4, float scale) {
    int i = blockIdx.x * blockDim.x + threadIdx.x;
    if (i >= n4) return;
    float4 v = ((const float4*)x)[i];
    __half2* yp = (__half2*)(y + (size_t)i * 4);
    yp[0] = __floats2half2_rn(v.x * scale, v.y * scale);
    yp[1] = __floats2half2_rn(v.z * scale, v.w * scale);
}

// ---------------------------------------------------------------------------
// Partial RoPE (first ROT=32 dims), in place on fp32.
// ---------------------------------------------------------------------------
__global__ void rope_kernel(float* __restrict__ x, const float* __restrict__ ct,
                            const float* __restrict__ st, int nheads, int total) {
    int idx = blockIdx.x * blockDim.x + threadIdx.x;
    if (idx >= total) return;
    int p  = idx & 15;
    int h  = (idx >> 4) % nheads;
    int bs = idx / (16 * nheads);
    float c = ct[bs * 32 + p];
    float s = st[bs * 32 + p];
    size_t base = ((size_t)bs * nheads + h) * 64;
    float x0 = x[base + p];
    float x1 = x[base + p + 16];
    x[base + p]      = x0 * c - x1 * s;
    x[base + p + 16] = x1 * c + x0 * s;
}

// ---------------------------------------------------------------------------
// V transpose to fp16: v[b][s][kvh][d] fp32 -> vht[b][kvh][d][S] half
// ---------------------------------------------------------------------------
__global__ void vT_half_kernel(const float* __restrict__ v,
                               __half* __restrict__ vh) {
    __shared__ float t[32][33];
    const int bkv = blockIdx.z;
    const int b = bkv / NKV, kvh = bkv % NKV;
    const int s0 = blockIdx.x * 32, d0 = blockIdx.y * 32;
    const int tx = threadIdx.x, ty = threadIdx.y;
#pragma unroll
    for (int j = 0; j < 32; j += 8) {
        int s = s0 + ty + j;
        t[ty + j][tx] = v[((size_t)(b * SEQ + s) * NKV + kvh) * HDIM + d0 + tx];
    }
    __syncthreads();
#pragma unroll
    for (int j = 0; j < 32; j += 8) {
        int d = d0 + ty + j;
        size_t o = ((size_t)(b * NKV + kvh) * HDIM + d) * SEQ + s0 + tx;
        vh[o] = __float2half_rn(t[tx][ty + j]);
    }
}

// ---------------------------------------------------------------------------
// Tensor-core GEMM — EXACT R5 version (scalar LDS frags, known 1546us).
// C = A @ W^T, 3-term bf16 split. CTA 128x128, 8 warps, BK=32, 2-stage.
// ---------------------------------------------------------------------------
#define LDS_STRIDE 40
#define ARR_BYTES  (128 * LDS_STRIDE * 2)
#define STAGE_BYTES (4 * ARR_BYTES)
#define GEMM_SMEM  (2 * STAGE_BYTES)

__global__ __launch_bounds__(256)
void gemm_mma(const __nv_bfloat16* __restrict__ Ah, const __nv_bfloat16* __restrict__ Al,
              const __nv_bfloat16* __restrict__ Bh, const __nv_bfloat16* __restrict__ Bl,
              float* __restrict__ C, int M, int N, int K) {
    extern __shared__ char smem[];

    const int tid = threadIdx.x;
    const int wid = tid >> 5;
    const int lane = tid & 31;
    const int wm = (wid >> 2) * 64;
    const int wn = (wid & 3) * 32;
    const int lr = lane >> 2;
    const int lk = (lane & 3) * 2;

    const int bm = blockIdx.y * 128;
    const int bn = blockIdx.x * 128;

    const int l_row0 = tid >> 2;
    const int l_cw   = (tid & 3) * 8;

    auto stage_ptr = [&](int s, int arr) -> char* {
        return smem + s * STAGE_BYTES + arr * ARR_BYTES;
    };

    auto prefetch = [&](int s, int k0) {
        const __nv_bfloat16* gsrc[4] = {Ah, Al, Bh, Bl};
#pragma unroll
        for (int t = 0; t < 4; t++) {
            const int rb = (t < 2) ? bm : bn;
            char* base = stage_ptr(s, t);
#pragma unroll
            for (int u = 0; u < 2; u++) {
                int row = l_row0 + u * 64;
                cp_async16(base + row * (LDS_STRIDE * 2) + l_cw * 2,
                           gsrc[t] + (size_t)(rb + row) * K + k0 + l_cw);
            }
        }
        CP_COMMIT();
    };

    float acc[4][4][4];
#pragma unroll
    for (int mi = 0; mi < 4; mi++)
#pragma unroll
        for (int ni = 0; ni < 4; ni++)
#pragma unroll
            for (int r = 0; r < 4; r++) acc[mi][ni][r] = 0.f;

    const int nchunk = K / 32;
    prefetch(0, 0);

    for (int ch = 0; ch < nchunk; ch++) {
        const int s = ch & 1;
        if (ch + 1 < nchunk) {
            prefetch(s ^ 1, (ch + 1) * 32);
            CP_WAIT(1);
        } else {
            CP_WAIT(0);
        }
        __syncthreads();

        const __nv_bfloat16* sAh = (const __nv_bfloat16*)stage_ptr(s, 0);
        const __nv_bfloat16* sAl = (const __nv_bfloat16*)stage_ptr(s, 1);
        const __nv_bfloat16* sBh = (const __nv_bfloat16*)stage_ptr(s, 2);
        const __nv_bfloat16* sBl = (const __nv_bfloat16*)stage_ptr(s, 3);

#pragma unroll
        for (int kk = 0; kk < 2; kk++) {
            const int k0 = kk * 16;
            uint32_t bh[4][2], bl[4][2];
#pragma unroll
            for (int ni = 0; ni < 4; ni++) {
                int n = wn + ni * 8 + lr;
                bh[ni][0] = *(const uint32_t*)&sBh[n * LDS_STRIDE + k0 + lk];
                bh[ni][1] = *(const uint32_t*)&sBh[n * LDS_STRIDE + k0 + lk + 8];
                bl[ni][0] = *(const uint32_t*)&sBl[n * LDS_STRIDE + k0 + lk];
                bl[ni][1] = *(const uint32_t*)&sBl[n * LDS_STRIDE + k0 + lk + 8];
            }
#pragma unroll
            for (int mi = 0; mi < 4; mi++) {
                int r0 = wm + mi * 16 + lr;
                uint32_t ah[4], al[4];
                ah[0] = *(const uint32_t*)&sAh[(r0    ) * LDS_STRIDE + k0 + lk];
                ah[1] = *(const uint32_t*)&sAh[(r0 + 8) * LDS_STRIDE + k0 + lk];
                ah[2] = *(const uint32_t*)&sAh[(r0    ) * LDS_STRIDE + k0 + lk + 8];
                ah[3] = *(const uint32_t*)&sAh[(r0 + 8) * LDS_STRIDE + k0 + lk + 8];
                al[0] = *(const uint32_t*)&sAl[(r0    ) * LDS_STRIDE + k0 + lk];
                al[1] = *(const uint32_t*)&sAl[(r0 + 8) * LDS_STRIDE + k0 + lk];
                al[2] = *(const uint32_t*)&sAl[(r0    ) * LDS_STRIDE + k0 + lk + 8];
                al[3] = *(const uint32_t*)&sAl[(r0 + 8) * LDS_STRIDE + k0 + lk + 8];
#pragma unroll
                for (int ni = 0; ni < 4; ni++) {
                    mma_bf16(acc[mi][ni], ah, bh[ni][0], bh[ni][1]);
                    mma_bf16(acc[mi][ni], ah, bl[ni][0], bl[ni][1]);
                    mma_bf16(acc[mi][ni], al, bh[ni][0], bh[ni][1]);
                }
            }
        }
        __syncthreads();
    }

#pragma unroll
    for (int mi = 0; mi < 4; mi++) {
        int row = bm + wm + mi * 16 + lr;
#pragma unroll
        for (int ni = 0; ni < 4; ni++) {
            int col = bn + wn + ni * 8 + lk;
            *(float2*)(C + (size_t)row * N + col) =
                make_float2(acc[mi][ni][0], acc[mi][ni][1]);
            *(float2*)(C + (size_t)(row + 8) * N + col) =
                make_float2(acc[mi][ni][2], acc[mi][ni][3]);
        }
    }
}

// ---------------------------------------------------------------------------
// Tensor-core flash attention — R5 structure, fp16 SINGLE-TERM MMAs.
// Grid (32, 64). 256 threads, 8 warps 2m x 4n. Tile 64 q x 64 keys.
// Q pre-scaled by 0.125. Output written as bf16 hi/lo (for bf16 O-proj).
// ---------------------------------------------------------------------------
#define KSTR  72
#define SSTRF 66
#define NEGBIG (-1e30f)
#define FLASH_SMEM (4 * 64 * KSTR * 2 + 64 * SSTRF * 4 + 3 * 64 * 4)

__global__ __launch_bounds__(256)
void flash_tc(const __half* __restrict__ qg, const __half* __restrict__ kg,
              const __half* __restrict__ vg,
              __nv_bfloat16* __restrict__ oh, __nv_bfloat16* __restrict__ ol) {
    extern __shared__ char smc[];
    __half* sQ = (__half*)smc;
    __half* sK = sQ + 64 * KSTR;
    __half* sV = sK + 64 * KSTR;   // [d][key]
    __half* sP = sV + 64 * KSTR;
    float* sS    = (float*)(sP + 64 * KSTR);
    float* row_m = sS + 64 * SSTRF;
    float* row_l = row_m + 64;
    float* row_a = row_l + 64;

    const int tid  = threadIdx.x;
    const int wid  = tid >> 5;
    const int lane = tid & 31;
    const int wm = (wid >> 2) * 32;
    const int wn = (wid & 3) * 16;
    const int lr = lane >> 2;
    const int lk = (lane & 3) * 2;

    const int qt  = gridDim.x - 1 - blockIdx.x;
    const int bh  = blockIdx.y;
    const int b   = bh >> 5;
    const int h   = bh & 31;
    const int kvh = h >> 2;

    // Q tile load (once): 64 rows x 8 x 16B
    {
        int slot = tid;             // 512 chunks over 2 iters
#pragma unroll
        for (int u = 0; u < 2; u++) {
            int sl = slot + 256 * u;
            int row = sl >> 3, cw = sl & 7;
            const size_t go = ((size_t)(b * SEQ + qt * 64 + row) * NHEAD + h) * HDIM + cw * 8;
            cp_async16(sQ + row * KSTR + cw * 8, qg + go);
        }
    }
    CP_COMMIT();

    if (tid < 64) { row_m[tid] = NEGBIG; row_l[tid] = 0.f; }

    float oacc[2][2][4];
#pragma unroll
    for (int mi = 0; mi < 2; mi++)
#pragma unroll
        for (int ni = 0; ni < 2; ni++)
#pragma unroll
            for (int r = 0; r < 4; r++) oacc[mi][ni][r] = 0.f;

    for (int kt = 0; kt <= qt; kt++) {
#pragma unroll
        for (int u = 0; u < 2; u++) {
            int sl = tid + 256 * u;
            int row = sl >> 3, cw = sl & 7;
            const size_t gk = ((size_t)(b * SEQ + kt * 64 + row) * NKV + kvh) * HDIM + cw * 8;
            cp_async16(sK + row * KSTR + cw * 8, kg + gk);
            const size_t gv = ((size_t)(b * NKV + kvh) * HDIM + row) * SEQ + kt * 64 + cw * 8;
            cp_async16(sV + row * KSTR + cw * 8, vg + gv);
        }
        CP_COMMIT();
        CP_WAIT(0);
        __syncthreads();

        // ---- S = Q @ K^T (fp16, single term) ----
        float sacc[2][2][4];
#pragma unroll
        for (int mi = 0; mi < 2; mi++)
#pragma unroll
            for (int ni = 0; ni < 2; ni++)
#pragma unroll
                for (int r = 0; r < 4; r++) sacc[mi][ni][r] = 0.f;

#pragma unroll
        for (int kk = 0; kk < 4; kk++) {
            const int k0 = kk * 16;
            uint32_t kb[2][2];
#pragma unroll
            for (int ni = 0; ni < 2; ni++) {
                int n = wn + ni * 8 + lr;
                kb[ni][0] = *(const uint32_t*)&sK[n * KSTR + k0 + lk];
                kb[ni][1] = *(const uint32_t*)&sK[n * KSTR + k0 + lk + 8];
            }
#pragma unroll
            for (int mi = 0; mi < 2; mi++) {
                int r0 = wm + mi * 16 + lr;
                uint32_t qa[4];
                qa[0] = *(const uint32_t*)&sQ[(r0    ) * KSTR + k0 + lk];
                qa[1] = *(const uint32_t*)&sQ[(r0 + 8) * KSTR + k0 + lk];
                qa[2] = *(const uint32_t*)&sQ[(r0    ) * KSTR + k0 + lk + 8];
                qa[3] = *(const uint32_t*)&sQ[(r0 + 8) * KSTR + k0 + lk + 8];
#pragma unroll
                for (int ni = 0; ni < 2; ni++)
                    mma_f16(sacc[mi][ni], qa, kb[ni][0], kb[ni][1]);
            }
        }

        // ---- mask + store scores ----
        const bool diag = (kt == qt);
#pragma unroll
        for (int mi = 0; mi < 2; mi++) {
#pragma unroll
            for (int ni = 0; ni < 2; ni++) {
                int r = wm + mi * 16 + lr;
                int c = wn + ni * 8 + lk;
                float s0 = sacc[mi][ni][0], s1 = sacc[mi][ni][1];
                float s2 = sacc[mi][ni][2], s3 = sacc[mi][ni][3];
                if (diag) {
                    if (c     > r)     s0 = NEGBIG;
                    if (c + 1 > r)     s1 = NEGBIG;
                    if (c     > r + 8) s2 = NEGBIG;
                    if (c + 1 > r + 8) s3 = NEGBIG;
                }
                *(float2*)&sS[r * SSTRF + c]       = make_float2(s0, s1);
                *(float2*)&sS[(r + 8) * SSTRF + c] = make_float2(s2, s3);
            }
        }
        __syncthreads();

        // ---- online softmax (4 threads/row) ----
        {
            const int row = tid >> 2, seg = tid & 3;
            const float* srow = sS + row * SSTRF + seg * 16;
            float mx = NEGBIG;
#pragma unroll
            for (int j = 0; j < 16; j++) mx = fmaxf(mx, srow[j]);
            mx = fmaxf(mx, __shfl_xor_sync(0xFFFFFFFF, mx, 1));
            mx = fmaxf(mx, __shfl_xor_sync(0xFFFFFFFF, mx, 2));
            const float mprev = row_m[row];
            const float mnew = fmaxf(mprev, mx);
            float sum = 0.f;
            __half* ph = sP + row * KSTR + seg * 16;
#pragma unroll
            for (int j = 0; j < 16; j++) {
                float p = __expf(srow[j] - mnew);
                sum += p;
                ph[j] = __float2half_rn(p);
            }
            sum += __shfl_xor_sync(0xFFFFFFFF, sum, 1);
            sum += __shfl_xor_sync(0xFFFFFFFF, sum, 2);
            if (seg == 0) {
                float alpha = __expf(mprev - mnew);
                row_a[row] = alpha;
                row_l[row] = row_l[row] * alpha + sum;
                row_m[row] = mnew;
            }
        }
        __syncthreads();

        // ---- rescale O, accumulate P @ V (fp16, single term) ----
#pragma unroll
        for (int mi = 0; mi < 2; mi++) {
            int r0 = wm + mi * 16 + lr;
            float a0 = row_a[r0], a1 = row_a[r0 + 8];
#pragma unroll
            for (int ni = 0; ni < 2; ni++) {
                oacc[mi][ni][0] *= a0; oacc[mi][ni][1] *= a0;
                oacc[mi][ni][2] *= a1; oacc[mi][ni][3] *= a1;
            }
        }
#pragma unroll
        for (int kk = 0; kk < 4; kk++) {
            const int k0 = kk * 16;
            uint32_t vb[2][2];
#pragma unroll
            for (int ni = 0; ni < 2; ni++) {
                int n = wn + ni * 8 + lr;     // d column
                vb[ni][0] = *(const uint32_t*)&sV[n * KSTR + k0 + lk];
                vb[ni][1] = *(const uint32_t*)&sV[n * KSTR + k0 + lk + 8];
            }
#pragma unroll
            for (int mi = 0; mi < 2; mi++) {
                int r0 = wm + mi * 16 + lr;
                uint32_t pa[4];
                pa[0] = *(const uint32_t*)&sP[(r0    ) * KSTR + k0 + lk];
                pa[1] = *(const uint32_t*)&sP[(r0 + 8) * KSTR + k0 + lk];
                pa[2] = *(const uint32_t*)&sP[(r0    ) * KSTR + k0 + lk + 8];
                pa[3] = *(const uint32_t*)&sP[(r0 + 8) * KSTR + k0 + lk + 8];
#pragma unroll
                for (int ni = 0; ni < 2; ni++)
                    mma_f16(oacc[mi][ni], pa, vb[ni][0], vb[ni][1]);
            }
        }
        __syncthreads();
    }

    // ---- normalize + write bf16 hi/lo output [b][s][h][d] ----
#pragma unroll
    for (int mi = 0; mi < 2; mi++) {
        int r = wm + mi * 16 + lr;
        float inv0 = 1.f / row_l[r];
        float inv1 = 1.f / row_l[r + 8];
#pragma unroll
        for (int ni = 0; ni < 2; ni++) {
            int c = wn + ni * 8 + lk;
            size_t o0 = ((size_t)(b * SEQ + qt * 64 + r) * NHEAD + h) * HDIM + c;
            size_t o1 = ((size_t)(b * SEQ + qt * 64 + r + 8) * NHEAD + h) * HDIM + c;
            float v0 = oacc[mi][ni][0] * inv0, v1 = oacc[mi][ni][1] * inv0;
            float v2 = oacc[mi][ni][2] * inv1, v3 = oacc[mi][ni][3] * inv1;
            __nv_bfloat16 h0 = __float2bfloat16(v0), h1 = __float2bfloat16(v1);
            __nv_bfloat16 h2 = __float2bfloat16(v2), h3 = __float2bfloat16(v3);
            *(__nv_bfloat162*)(oh + o0) = __nv_bfloat162(h0, h1);
            *(__nv_bfloat162*)(oh + o1) = __nv_bfloat162(h2, h3);
            *(__nv_bfloat162*)(ol + o0) = __nv_bfloat162(
                __float2bfloat16(v0 - __bfloat162float(h0)),
                __float2bfloat16(v1 - __bfloat162float(h1)));
            *(__nv_bfloat162*)(ol + o1) = __nv_bfloat162(
                __float2bfloat16(v2 - __bfloat162float(h2)),
                __float2bfloat16(v3 - __bfloat162float(h3)));
        }
    }
}

// ---------------------------------------------------------------------------
// Host launcher
// Inputs: 0 hidden 1 cos 2 sin 3 mask(unused) 4 Wq 5 Wk 6 Wv 7 Wo
// ---------------------------------------------------------------------------
extern "C" void kernel_launch(void* const* d_in, const int* in_sizes, int n_in,
                              void* d_out, int out_size) {
    const float* hidden = (const float*)d_in[0];
    const float* cosb   = (const float*)d_in[1];
    const float* sinb   = (const float*)d_in[2];
    const float* Wq     = (const float*)d_in[4];
    const float* Wk     = (const float*)d_in[5];
    const float* Wv     = (const float*)d_in[6];
    const float* Wo     = (const float*)d_in[7];
    float* out = (float*)d_out;

    float *qp, *kp, *vp;
    cudaGetSymbolAddress((void**)&qp, g_q);
    cudaGetSymbolAddress((void**)&kp, g_k);
    cudaGetSymbolAddress((void**)&vp, g_v);

    __nv_bfloat16 *ah, *al, *oh, *ol, *wqh, *wql, *wkh, *wkl, *wvh, *wvl, *woh, *wol;
    __half *qhp, *khp, *vhtp;
    cudaGetSymbolAddress((void**)&ah, g_ah);   cudaGetSymbolAddress((void**)&al, g_al);
    cudaGetSymbolAddress((void**)&oh, g_oh);   cudaGetSymbolAddress((void**)&ol, g_ol);
    cudaGetSymbolAddress((void**)&wqh, g_wqh); cudaGetSymbolAddress((void**)&wql, g_wql);
    cudaGetSymbolAddress((void**)&wkh, g_wkh); cudaGetSymbolAddress((void**)&wkl, g_wkl);
    cudaGetSymbolAddress((void**)&wvh, g_wvh); cudaGetSymbolAddress((void**)&wvl, g_wvl);
    cudaGetSymbolAddress((void**)&woh, g_woh); cudaGetSymbolAddress((void**)&wol, g_wol);
    cudaGetSymbolAddress((void**)&qhp, g_qh);
    cudaGetSymbolAddress((void**)&khp, g_kh);
    cudaGetSymbolAddress((void**)&vhtp, g_vht);

    const int M = NBATCH * SEQ;  // 4096

    cudaFuncSetAttribute(gemm_mma, cudaFuncAttributeMaxDynamicSharedMemorySize,
                         GEMM_SMEM);
    cudaFuncSetAttribute(flash_tc, cudaFuncAttributeMaxDynamicSharedMemorySize,
                         FLASH_SMEM);

    // bf16 hi/lo splits of inputs
    int n4h = (M * HID) / 4;
    split_kernel<<<(n4h + 255) / 256, 256>>>(hidden, ah, al, n4h);
    int n4q = (2048 * 2048) / 4;
    split_kernel<<<(n4q + 255) / 256, 256>>>(Wq, wqh, wql, n4q);
    split_kernel<<<(n4q + 255) / 256, 256>>>(Wo, woh, wol, n4q);
    int n4k = (512 * 2048) / 4;
    split_kernel<<<(n4k + 255) / 256, 256>>>(Wk, wkh, wkl, n4k);
    split_kernel<<<(n4k + 255) / 256, 256>>>(Wv, wvh, wvl, n4k);

    // QKV projections (bf16 3-term, fp32 out)
    gemm_mma<<<dim3(2048 / 128, M / 128), 256, GEMM_SMEM>>>(ah, al, wqh, wql, qp, M, 2048, 2048);
    gemm_mma<<<dim3(512  / 128, M / 128), 256, GEMM_SMEM>>>(ah, al, wkh, wkl, kp, M, 512, 2048);
    gemm_mma<<<dim3(512  / 128, M / 128), 256, GEMM_SMEM>>>(ah, al, wvh, wvl, vp, M, 512, 2048);

    // Partial RoPE (fp32, in place)
    int totq = M * NHEAD * 16;
    rope_kernel<<<(totq + 255) / 256, 256>>>(qp, cosb, sinb, NHEAD, totq);
    int totk = M * NKV * 16;
    rope_kernel<<<(totk + 255) / 256, 256>>>(kp, cosb, sinb, NKV, totk);

    // fp16 attention operands (Q scaled by 1/sqrt(D))
    int n4qa = (M * NHEAD * HDIM) / 4;
    tohalf_kernel<<<(n4qa + 255) / 256, 256>>>(qp, qhp, n4qa, 0.125f);
    int n4ka = (M * NKV * HDIM) / 4;
    tohalf_kernel<<<(n4ka + 255) / 256, 256>>>(kp, khp, n4ka, 1.f);
    vT_half_kernel<<<dim3(SEQ / 32, HDIM / 32, NBATCH * NKV), dim3(32, 8)>>>(vp, vhtp);

    // fp16 single-term flash attention
    flash_tc<<<dim3(SEQ / 64, NBATCH * NHEAD), 256, FLASH_SMEM>>>(
        qhp, khp, vhtp, oh, ol);

    // Output projection (bf16 3-term)
    gemm_mma<<<dim3(2048 / 128, M / 128), 256, GEMM_SMEM>>>(oh, ol, woh, wol, out, M, 2048, 2048);
}

// round 11
// speedup vs baseline: 1.5931x; 1.2453x over previous
#include <cuda_runtime.h>
#include <cuda_bf16.h>
#include <cuda_fp16.h>
#include <cstdint>
#include <math.h>

// Problem: B=2, S=2048, HID=2048, H=32, KVH=8, D=64, G=4, ROT=32
#define NBATCH 2
#define SEQ    2048
#define HID    2048
#define NHEAD  32
#define NKV    8
#define HDIM   64

// Power-of-2 scale keeping fp16 split residuals in the normal range.
#define ASPLIT_SCALE 512.f
#define ASPLIT_INV   (1.f / 512.f)

// ---------------------------------------------------------------------------
// Scratch (device globals; no allocations allowed)
// ---------------------------------------------------------------------------
__device__ float g_q[NBATCH*SEQ*NHEAD*HDIM];
__device__ float g_k[NBATCH*SEQ*NKV*HDIM];
__device__ float g_v[NBATCH*SEQ*NKV*HDIM];

// fp16 2-term GEMM operands
__device__ __half g_ah2[4096*2048], g_al2[4096*2048];   // hidden (x512, hi/lo)
__device__ __half g_oh2[4096*2048], g_ol2[4096*2048];   // attn out (x512, hi/lo)
__device__ __half g_w16q[2048*2048];
__device__ __half g_w16k[512*2048];
__device__ __half g_w16v[512*2048];
__device__ __half g_w16o[2048*2048];
// fp16 attention operands
__device__ __half g_qh[NBATCH*SEQ*NHEAD*HDIM];
__device__ __half g_kh[NBATCH*SEQ*NKV*HDIM];
__device__ __half g_vht[NBATCH*NKV*HDIM*SEQ];   // [b][kvh][d][S]

// ---------------------------------------------------------------------------
// helpers
// ---------------------------------------------------------------------------
__device__ __forceinline__ void mma_f16(float* c, const uint32_t* a,
                                        uint32_t b0, uint32_t b1) {
    asm volatile(
        "mma.sync.aligned.m16n8k16.row.col.f32.f16.f16.f32 "
        "{%0,%1,%2,%3}, {%4,%5,%6,%7}, {%8,%9}, {%0,%1,%2,%3};"
        : "+f"(c[0]), "+f"(c[1]), "+f"(c[2]), "+f"(c[3])
        : "r"(a[0]), "r"(a[1]), "r"(a[2]), "r"(a[3]), "r"(b0), "r"(b1));
}
__device__ __forceinline__ void cp_async16(void* smem_dst, const void* gsrc) {
    uint32_t d;
    asm("{ .reg .u64 t; cvta.to.shared.u64 t, %1; cvt.u32.u64 %0, t; }"
        : "=r"(d) : "l"(smem_dst));
    asm volatile("cp.async.cg.shared.global [%0], [%1], 16;" :: "r"(d), "l"(gsrc));
}
#define CP_COMMIT() asm volatile("cp.async.commit_group;" ::: "memory")
#define CP_WAIT(n)  asm volatile("cp.async.wait_group %0;" :: "n"(n) : "memory")

// ---------------------------------------------------------------------------
// fp32 -> fp16 (hi, lo) split with scale, vectorized x4
// ---------------------------------------------------------------------------
__global__ void split16_kernel(const float* __restrict__ x,
                               __half* __restrict__ hi,
                               __half* __restrict__ lo, int n4, float scale) {
    int i = blockIdx.x * blockDim.x + threadIdx.x;
    if (i >= n4) return;
    float4 v = ((const float4*)x)[i];
    v.x *= scale; v.y *= scale; v.z *= scale; v.w *= scale;
    __half h0 = __float2half_rn(v.x);
    __half h1 = __float2half_rn(v.y);
    __half h2 = __float2half_rn(v.z);
    __half h3 = __float2half_rn(v.w);
    __half2* hp = (__half2*)(hi + (size_t)i * 4);
    __half2* lp = (__half2*)(lo + (size_t)i * 4);
    hp[0] = __half2(h0, h1); hp[1] = __half2(h2, h3);
    lp[0] = __half2(__float2half_rn(v.x - __half2float(h0)),
                    __float2half_rn(v.y - __half2float(h1)));
    lp[1] = __half2(__float2half_rn(v.z - __half2float(h2)),
                    __float2half_rn(v.w - __half2float(h3)));
}

// ---------------------------------------------------------------------------
// fp32 -> fp16 with scale, vectorized x4
// ---------------------------------------------------------------------------
__global__ void tohalf_kernel(const float* __restrict__ x,
                              __half* __restrict__ y, int n4, float scale) {
    int i = blockIdx.x * blockDim.x + threadIdx.x;
    if (i >= n4) return;
    float4 v = ((const float4*)x)[i];
    __half2* yp = (__half2*)(y + (size_t)i * 4);
    yp[0] = __floats2half2_rn(v.x * scale, v.y * scale);
    yp[1] = __floats2half2_rn(v.z * scale, v.w * scale);
}

// ---------------------------------------------------------------------------
// Partial RoPE (first ROT=32 dims), in place on fp32.
// ---------------------------------------------------------------------------
__global__ void rope_kernel(float* __restrict__ x, const float* __restrict__ ct,
                            const float* __restrict__ st, int nheads, int total) {
    int idx = blockIdx.x * blockDim.x + threadIdx.x;
    if (idx >= total) return;
    int p  = idx & 15;
    int h  = (idx >> 4) % nheads;
    int bs = idx / (16 * nheads);
    float c = ct[bs * 32 + p];
    float s = st[bs * 32 + p];
    size_t base = ((size_t)bs * nheads + h) * 64;
    float x0 = x[base + p];
    float x1 = x[base + p + 16];
    x[base + p]      = x0 * c - x1 * s;
    x[base + p + 16] = x1 * c + x0 * s;
}

// ---------------------------------------------------------------------------
// V transpose to fp16: v[b][s][kvh][d] fp32 -> vht[b][kvh][d][S] half
// ---------------------------------------------------------------------------
__global__ void vT_half_kernel(const float* __restrict__ v,
                               __half* __restrict__ vh) {
    __shared__ float t[32][33];
    const int bkv = blockIdx.z;
    const int b = bkv / NKV, kvh = bkv % NKV;
    const int s0 = blockIdx.x * 32, d0 = blockIdx.y * 32;
    const int tx = threadIdx.x, ty = threadIdx.y;
#pragma unroll
    for (int j = 0; j < 32; j += 8) {
        int s = s0 + ty + j;
        t[ty + j][tx] = v[((size_t)(b * SEQ + s) * NKV + kvh) * HDIM + d0 + tx];
    }
    __syncthreads();
#pragma unroll
    for (int j = 0; j < 32; j += 8) {
        int d = d0 + ty + j;
        size_t o = ((size_t)(b * NKV + kvh) * HDIM + d) * SEQ + s0 + tx;
        vh[o] = __float2half_rn(t[tx][ty + j]);
    }
}

// ---------------------------------------------------------------------------
// Tensor-core GEMM, fp16 2-term: C = (Ah + Al) @ B^T * outscale.
// A pre-scaled by 512 (hi/lo fp16), B single fp16, fp32 accumulate.
// R5-proven structure: CTA 128x128, 8 warps (2m x 4n), BK=32, 2-stage
// cp.async with prefetch-before-wait, scalar LDS fragment loads.
// ---------------------------------------------------------------------------
#define LDS_STRIDE 40
#define ARR_BYTES  (128 * LDS_STRIDE * 2)     // 10240
#define STAGE_BYTES (3 * ARR_BYTES)           // 30720
#define GEMM_SMEM  (2 * STAGE_BYTES)          // 61440

__global__ __launch_bounds__(256)
void gemm_mma16(const __half* __restrict__ Ah, const __half* __restrict__ Al,
                const __half* __restrict__ B,
                float* __restrict__ C, float outscale, int M, int N, int K) {
    extern __shared__ char smem[];

    const int tid = threadIdx.x;
    const int wid = tid >> 5;
    const int lane = tid & 31;
    const int wm = (wid >> 2) * 64;
    const int wn = (wid & 3) * 32;
    const int lr = lane >> 2;
    const int lk = (lane & 3) * 2;

    const int bm = blockIdx.y * 128;
    const int bn = blockIdx.x * 128;

    const int l_row0 = tid >> 2;
    const int l_cw   = (tid & 3) * 8;

    auto stage_ptr = [&](int s, int arr) -> char* {
        return smem + s * STAGE_BYTES + arr * ARR_BYTES;
    };

    auto prefetch = [&](int s, int k0) {
        const __half* gsrc[3] = {Ah, Al, B};
#pragma unroll
        for (int t = 0; t < 3; t++) {
            const int rb = (t < 2) ? bm : bn;
            char* base = stage_ptr(s, t);
#pragma unroll
            for (int u = 0; u < 2; u++) {
                int row = l_row0 + u * 64;
                cp_async16(base + row * (LDS_STRIDE * 2) + l_cw * 2,
                           gsrc[t] + (size_t)(rb + row) * K + k0 + l_cw);
            }
        }
        CP_COMMIT();
    };

    float acc[4][4][4];
#pragma unroll
    for (int mi = 0; mi < 4; mi++)
#pragma unroll
        for (int ni = 0; ni < 4; ni++)
#pragma unroll
            for (int r = 0; r < 4; r++) acc[mi][ni][r] = 0.f;

    const int nchunk = K / 32;
    prefetch(0, 0);

    for (int ch = 0; ch < nchunk; ch++) {
        const int s = ch & 1;
        if (ch + 1 < nchunk) {
            prefetch(s ^ 1, (ch + 1) * 32);
            CP_WAIT(1);
        } else {
            CP_WAIT(0);
        }
        __syncthreads();

        const __half* sAh = (const __half*)stage_ptr(s, 0);
        const __half* sAl = (const __half*)stage_ptr(s, 1);
        const __half* sB  = (const __half*)stage_ptr(s, 2);

#pragma unroll
        for (int kk = 0; kk < 2; kk++) {
            const int k0 = kk * 16;
            uint32_t bf[4][2];
#pragma unroll
            for (int ni = 0; ni < 4; ni++) {
                int n = wn + ni * 8 + lr;
                bf[ni][0] = *(const uint32_t*)&sB[n * LDS_STRIDE + k0 + lk];
                bf[ni][1] = *(const uint32_t*)&sB[n * LDS_STRIDE + k0 + lk + 8];
            }
#pragma unroll
            for (int mi = 0; mi < 4; mi++) {
                int r0 = wm + mi * 16 + lr;
                uint32_t ah[4], al[4];
                ah[0] = *(const uint32_t*)&sAh[(r0    ) * LDS_STRIDE + k0 + lk];
                ah[1] = *(const uint32_t*)&sAh[(r0 + 8) * LDS_STRIDE + k0 + lk];
                ah[2] = *(const uint32_t*)&sAh[(r0    ) * LDS_STRIDE + k0 + lk + 8];
                ah[3] = *(const uint32_t*)&sAh[(r0 + 8) * LDS_STRIDE + k0 + lk + 8];
                al[0] = *(const uint32_t*)&sAl[(r0    ) * LDS_STRIDE + k0 + lk];
                al[1] = *(const uint32_t*)&sAl[(r0 + 8) * LDS_STRIDE + k0 + lk];
                al[2] = *(const uint32_t*)&sAl[(r0    ) * LDS_STRIDE + k0 + lk + 8];
                al[3] = *(const uint32_t*)&sAl[(r0 + 8) * LDS_STRIDE + k0 + lk + 8];
#pragma unroll
                for (int ni = 0; ni < 4; ni++) {
                    mma_f16(acc[mi][ni], ah, bf[ni][0], bf[ni][1]);
                    mma_f16(acc[mi][ni], al, bf[ni][0], bf[ni][1]);
                }
            }
        }
        __syncthreads();
    }

#pragma unroll
    for (int mi = 0; mi < 4; mi++) {
        int row = bm + wm + mi * 16 + lr;
#pragma unroll
        for (int ni = 0; ni < 4; ni++) {
            int col = bn + wn + ni * 8 + lk;
            *(float2*)(C + (size_t)row * N + col) =
                make_float2(acc[mi][ni][0] * outscale, acc[mi][ni][1] * outscale);
            *(float2*)(C + (size_t)(row + 8) * N + col) =
                make_float2(acc[mi][ni][2] * outscale, acc[mi][ni][3] * outscale);
        }
    }
}

// ---------------------------------------------------------------------------
// Tensor-core flash attention — R10 version (fp16 single-term), epilogue
// now writes fp16 hi/lo (x512) for the fp16 O-projection.
// ---------------------------------------------------------------------------
#define KSTR  72
#define SSTRF 66
#define NEGBIG (-1e30f)
#define FLASH_SMEM (4 * 64 * KSTR * 2 + 64 * SSTRF * 4 + 3 * 64 * 4)

__global__ __launch_bounds__(256)
void flash_tc(const __half* __restrict__ qg, const __half* __restrict__ kg,
              const __half* __restrict__ vg,
              __half* __restrict__ oh, __half* __restrict__ ol) {
    extern __shared__ char smc[];
    __half* sQ = (__half*)smc;
    __half* sK = sQ + 64 * KSTR;
    __half* sV = sK + 64 * KSTR;   // [d][key]
    __half* sP = sV + 64 * KSTR;
    float* sS    = (float*)(sP + 64 * KSTR);
    float* row_m = sS + 64 * SSTRF;
    float* row_l = row_m + 64;
    float* row_a = row_l + 64;

    const int tid  = threadIdx.x;
    const int wid  = tid >> 5;
    const int lane = tid & 31;
    const int wm = (wid >> 2) * 32;
    const int wn = (wid & 3) * 16;
    const int lr = lane >> 2;
    const int lk = (lane & 3) * 2;

    const int qt  = gridDim.x - 1 - blockIdx.x;
    const int bh  = blockIdx.y;
    const int b   = bh >> 5;
    const int h   = bh & 31;
    const int kvh = h >> 2;

#pragma unroll
    for (int u = 0; u < 2; u++) {
        int sl = tid + 256 * u;
        int row = sl >> 3, cw = sl & 7;
        const size_t go = ((size_t)(b * SEQ + qt * 64 + row) * NHEAD + h) * HDIM + cw * 8;
        cp_async16(sQ + row * KSTR + cw * 8, qg + go);
    }
    CP_COMMIT();

    if (tid < 64) { row_m[tid] = NEGBIG; row_l[tid] = 0.f; }

    float oacc[2][2][4];
#pragma unroll
    for (int mi = 0; mi < 2; mi++)
#pragma unroll
        for (int ni = 0; ni < 2; ni++)
#pragma unroll
            for (int r = 0; r < 4; r++) oacc[mi][ni][r] = 0.f;

    for (int kt = 0; kt <= qt; kt++) {
#pragma unroll
        for (int u = 0; u < 2; u++) {
            int sl = tid + 256 * u;
            int row = sl >> 3, cw = sl & 7;
            const size_t gk = ((size_t)(b * SEQ + kt * 64 + row) * NKV + kvh) * HDIM + cw * 8;
            cp_async16(sK + row * KSTR + cw * 8, kg + gk);
            const size_t gv = ((size_t)(b * NKV + kvh) * HDIM + row) * SEQ + kt * 64 + cw * 8;
            cp_async16(sV + row * KSTR + cw * 8, vg + gv);
        }
        CP_COMMIT();
        CP_WAIT(0);
        __syncthreads();

        // ---- S = Q @ K^T ----
        float sacc[2][2][4];
#pragma unroll
        for (int mi = 0; mi < 2; mi++)
#pragma unroll
            for (int ni = 0; ni < 2; ni++)
#pragma unroll
                for (int r = 0; r < 4; r++) sacc[mi][ni][r] = 0.f;

#pragma unroll
        for (int kk = 0; kk < 4; kk++) {
            const int k0 = kk * 16;
            uint32_t kb[2][2];
#pragma unroll
            for (int ni = 0; ni < 2; ni++) {
                int n = wn + ni * 8 + lr;
                kb[ni][0] = *(const uint32_t*)&sK[n * KSTR + k0 + lk];
                kb[ni][1] = *(const uint32_t*)&sK[n * KSTR + k0 + lk + 8];
            }
#pragma unroll
            for (int mi = 0; mi < 2; mi++) {
                int r0 = wm + mi * 16 + lr;
                uint32_t qa[4];
                qa[0] = *(const uint32_t*)&sQ[(r0    ) * KSTR + k0 + lk];
                qa[1] = *(const uint32_t*)&sQ[(r0 + 8) * KSTR + k0 + lk];
                qa[2] = *(const uint32_t*)&sQ[(r0    ) * KSTR + k0 + lk + 8];
                qa[3] = *(const uint32_t*)&sQ[(r0 + 8) * KSTR + k0 + lk + 8];
#pragma unroll
                for (int ni = 0; ni < 2; ni++)
                    mma_f16(sacc[mi][ni], qa, kb[ni][0], kb[ni][1]);
            }
        }

        // ---- mask + store scores ----
        const bool diag = (kt == qt);
#pragma unroll
        for (int mi = 0; mi < 2; mi++) {
#pragma unroll
            for (int ni = 0; ni < 2; ni++) {
                int r = wm + mi * 16 + lr;
                int c = wn + ni * 8 + lk;
                float s0 = sacc[mi][ni][0], s1 = sacc[mi][ni][1];
                float s2 = sacc[mi][ni][2], s3 = sacc[mi][ni][3];
                if (diag) {
                    if (c     > r)     s0 = NEGBIG;
                    if (c + 1 > r)     s1 = NEGBIG;
                    if (c     > r + 8) s2 = NEGBIG;
                    if (c + 1 > r + 8) s3 = NEGBIG;
                }
                *(float2*)&sS[r * SSTRF + c]       = make_float2(s0, s1);
                *(float2*)&sS[(r + 8) * SSTRF + c] = make_float2(s2, s3);
            }
        }
        __syncthreads();

        // ---- online softmax (4 threads/row) ----
        {
            const int row = tid >> 2, seg = tid & 3;
            const float* srow = sS + row * SSTRF + seg * 16;
            float mx = NEGBIG;
#pragma unroll
            for (int j = 0; j < 16; j++) mx = fmaxf(mx, srow[j]);
            mx = fmaxf(mx, __shfl_xor_sync(0xFFFFFFFF, mx, 1));
            mx = fmaxf(mx, __shfl_xor_sync(0xFFFFFFFF, mx, 2));
            const float mprev = row_m[row];
            const float mnew = fmaxf(mprev, mx);
            float sum = 0.f;
            __half* ph = sP + row * KSTR + seg * 16;
#pragma unroll
            for (int j = 0; j < 16; j++) {
                float p = __expf(srow[j] - mnew);
                sum += p;
                ph[j] = __float2half_rn(p);
            }
            sum += __shfl_xor_sync(0xFFFFFFFF, sum, 1);
            sum += __shfl_xor_sync(0xFFFFFFFF, sum, 2);
            if (seg == 0) {
                float alpha = __expf(mprev - mnew);
                row_a[row] = alpha;
                row_l[row] = row_l[row] * alpha + sum;
                row_m[row] = mnew;
            }
        }
        __syncthreads();

        // ---- rescale O, accumulate P @ V ----
#pragma unroll
        for (int mi = 0; mi < 2; mi++) {
            int r0 = wm + mi * 16 + lr;
            float a0 = row_a[r0], a1 = row_a[r0 + 8];
#pragma unroll
            for (int ni = 0; ni < 2; ni++) {
                oacc[mi][ni][0] *= a0; oacc[mi][ni][1] *= a0;
                oacc[mi][ni][2] *= a1; oacc[mi][ni][3] *= a1;
            }
        }
#pragma unroll
        for (int kk = 0; kk < 4; kk++) {
            const int k0 = kk * 16;
            uint32_t vb[2][2];
#pragma unroll
            for (int ni = 0; ni < 2; ni++) {
                int n = wn + ni * 8 + lr;
                vb[ni][0] = *(const uint32_t*)&sV[n * KSTR + k0 + lk];
                vb[ni][1] = *(const uint32_t*)&sV[n * KSTR + k0 + lk + 8];
            }
#pragma unroll
            for (int mi = 0; mi < 2; mi++) {
                int r0 = wm + mi * 16 + lr;
                uint32_t pa[4];
                pa[0] = *(const uint32_t*)&sP[(r0    ) * KSTR + k0 + lk];
                pa[1] = *(const uint32_t*)&sP[(r0 + 8) * KSTR + k0 + lk];
                pa[2] = *(const uint32_t*)&sP[(r0    ) * KSTR + k0 + lk + 8];
                pa[3] = *(const uint32_t*)&sP[(r0 + 8) * KSTR + k0 + lk + 8];
#pragma unroll
                for (int ni = 0; ni < 2; ni++)
                    mma_f16(oacc[mi][ni], pa, vb[ni][0], vb[ni][1]);
            }
        }
        __syncthreads();
    }

    // ---- normalize + write fp16 hi/lo (x512) output [b][s][h][d] ----
#pragma unroll
    for (int mi = 0; mi < 2; mi++) {
        int r = wm + mi * 16 + lr;
        float inv0 = ASPLIT_SCALE / row_l[r];
        float inv1 = ASPLIT_SCALE / row_l[r + 8];
#pragma unroll
        for (int ni = 0; ni < 2; ni++) {
            int c = wn + ni * 8 + lk;
            size_t o0 = ((size_t)(b * SEQ + qt * 64 + r) * NHEAD + h) * HDIM + c;
            size_t o1 = ((size_t)(b * SEQ + qt * 64 + r + 8) * NHEAD + h) * HDIM + c;
            float v0 = oacc[mi][ni][0] * inv0, v1 = oacc[mi][ni][1] * inv0;
            float v2 = oacc[mi][ni][2] * inv1, v3 = oacc[mi][ni][3] * inv1;
            __half h0 = __float2half_rn(v0), h1 = __float2half_rn(v1);
            __half h2 = __float2half_rn(v2), h3 = __float2half_rn(v3);
            *(__half2*)(oh + o0) = __half2(h0, h1);
            *(__half2*)(oh + o1) = __half2(h2, h3);
            *(__half2*)(ol + o0) = __half2(__float2half_rn(v0 - __half2float(h0)),
                                           __float2half_rn(v1 - __half2float(h1)));
            *(__half2*)(ol + o1) = __half2(__float2half_rn(v2 - __half2float(h2)),
                                           __float2half_rn(v3 - __half2float(h3)));
        }
    }
}

// ---------------------------------------------------------------------------
// Host launcher
// Inputs: 0 hidden 1 cos 2 sin 3 mask(unused) 4 Wq 5 Wk 6 Wv 7 Wo
// ---------------------------------------------------------------------------
extern "C" void kernel_launch(void* const* d_in, const int* in_sizes, int n_in,
                              void* d_out, int out_size) {
    const float* hidden = (const float*)d_in[0];
    const float* cosb   = (const float*)d_in[1];
    const float* sinb   = (const float*)d_in[2];
    const float* Wq     = (const float*)d_in[4];
    const float* Wk     = (const float*)d_in[5];
    const float* Wv     = (const float*)d_in[6];
    const float* Wo     = (const float*)d_in[7];
    float* out = (float*)d_out;

    float *qp, *kp, *vp;
    cudaGetSymbolAddress((void**)&qp, g_q);
    cudaGetSymbolAddress((void**)&kp, g_k);
    cudaGetSymbolAddress((void**)&vp, g_v);

    __half *ah2, *al2, *oh2, *ol2, *w16q, *w16k, *w16v, *w16o;
    __half *qhp, *khp, *vhtp;
    cudaGetSymbolAddress((void**)&ah2, g_ah2);   cudaGetSymbolAddress((void**)&al2, g_al2);
    cudaGetSymbolAddress((void**)&oh2, g_oh2);   cudaGetSymbolAddress((void**)&ol2, g_ol2);
    cudaGetSymbolAddress((void**)&w16q, g_w16q); cudaGetSymbolAddress((void**)&w16k, g_w16k);
    cudaGetSymbolAddress((void**)&w16v, g_w16v); cudaGetSymbolAddress((void**)&w16o, g_w16o);
    cudaGetSymbolAddress((void**)&qhp, g_qh);
    cudaGetSymbolAddress((void**)&khp, g_kh);
    cudaGetSymbolAddress((void**)&vhtp, g_vht);

    const int M = NBATCH * SEQ;  // 4096

    cudaFuncSetAttribute(gemm_mma16, cudaFuncAttributeMaxDynamicSharedMemorySize,
                         GEMM_SMEM);
    cudaFuncSetAttribute(flash_tc, cudaFuncAttributeMaxDynamicSharedMemorySize,
                         FLASH_SMEM);

    // Operand conversions
    int n4h = (M * HID) / 4;
    split16_kernel<<<(n4h + 255) / 256, 256>>>(hidden, ah2, al2, n4h, ASPLIT_SCALE);
    int n4q = (2048 * 2048) / 4;
    tohalf_kernel<<<(n4q + 255) / 256, 256>>>(Wq, w16q, n4q, 1.f);
    tohalf_kernel<<<(n4q + 255) / 256, 256>>>(Wo, w16o, n4q, 1.f);
    int n4k = (512 * 2048) / 4;
    tohalf_kernel<<<(n4k + 255) / 256, 256>>>(Wk, w16k, n4k, 1.f);
    tohalf_kernel<<<(n4k + 255) / 256, 256>>>(Wv, w16v, n4k, 1.f);

    // QKV projections (fp16 2-term, fp32 out, undo x512)
    gemm_mma16<<<dim3(2048 / 128, M / 128), 256, GEMM_SMEM>>>(
        ah2, al2, w16q, qp, ASPLIT_INV, M, 2048, 2048);
    gemm_mma16<<<dim3(512 / 128, M / 128), 256, GEMM_SMEM>>>(
        ah2, al2, w16k, kp, ASPLIT_INV, M, 512, 2048);
    gemm_mma16<<<dim3(512 / 128, M / 128), 256, GEMM_SMEM>>>(
        ah2, al2, w16v, vp, ASPLIT_INV, M, 512, 2048);

    // Partial RoPE (fp32, in place)
    int totq = M * NHEAD * 16;
    rope_kernel<<<(totq + 255) / 256, 256>>>(qp, cosb, sinb, NHEAD, totq);
    int totk = M * NKV * 16;
    rope_kernel<<<(totk + 255) / 256, 256>>>(kp, cosb, sinb, NKV, totk);

    // fp16 attention operands (Q scaled by 1/sqrt(D))
    int n4qa = (M * NHEAD * HDIM) / 4;
    tohalf_kernel<<<(n4qa + 255) / 256, 256>>>(qp, qhp, n4qa, 0.125f);
    int n4ka = (M * NKV * HDIM) / 4;
    tohalf_kernel<<<(n4ka + 255) / 256, 256>>>(kp, khp, n4ka, 1.f);
    vT_half_kernel<<<dim3(SEQ / 32, HDIM / 32, NBATCH * NKV), dim3(32, 8)>>>(vp, vhtp);

    // fp16 single-term flash attention -> fp16 hi/lo (x512)
    flash_tc<<<dim3(SEQ / 64, NBATCH * NHEAD), 256, FLASH_SMEM>>>(
        qhp, khp, vhtp, oh2, ol2);

    // Output projection (fp16 2-term, undo x512)
    gemm_mma16<<<dim3(2048 / 128, M / 128), 256, GEMM_SMEM>>>(
        oh2, ol2, w16o, out, ASPLIT_INV, M, 2048, 2048);
}

// round 12
// speedup vs baseline: 2.0426x; 1.2821x over previous
#include <cuda_runtime.h>
#include <cuda_fp16.h>
#include <cstdint>
#include <math.h>

// Problem: B=2, S=2048, HID=2048, H=32, KVH=8, D=64, G=4, ROT=32
#define NBATCH 2
#define SEQ    2048
#define HID    2048
#define NHEAD  32
#define NKV    8
#define HDIM   64

// ---------------------------------------------------------------------------
// Scratch (device globals; no allocations allowed)
// ---------------------------------------------------------------------------
__device__ float g_q[NBATCH*SEQ*NHEAD*HDIM];
__device__ float g_k[NBATCH*SEQ*NKV*HDIM];
__device__ float g_v[NBATCH*SEQ*NKV*HDIM];

__device__ __half g_a16[4096*2048];     // hidden fp16
__device__ __half g_o16[4096*2048];     // attn out fp16
__device__ __half g_w16q[2048*2048];
__device__ __half g_w16k[512*2048];
__device__ __half g_w16v[512*2048];
__device__ __half g_w16o[2048*2048];
// fp16 attention operands
__device__ __half g_qh[NBATCH*SEQ*NHEAD*HDIM];
__device__ __half g_kh[NBATCH*SEQ*NKV*HDIM];
__device__ __half g_vht[NBATCH*NKV*HDIM*SEQ];   // [b][kvh][d][S]

// ---------------------------------------------------------------------------
// helpers
// ---------------------------------------------------------------------------
__device__ __forceinline__ void mma_f16(float* c, const uint32_t* a,
                                        uint32_t b0, uint32_t b1) {
    asm volatile(
        "mma.sync.aligned.m16n8k16.row.col.f32.f16.f16.f32 "
        "{%0,%1,%2,%3}, {%4,%5,%6,%7}, {%8,%9}, {%0,%1,%2,%3};"
        : "+f"(c[0]), "+f"(c[1]), "+f"(c[2]), "+f"(c[3])
        : "r"(a[0]), "r"(a[1]), "r"(a[2]), "r"(a[3]), "r"(b0), "r"(b1));
}
__device__ __forceinline__ void cp_async16(void* smem_dst, const void* gsrc) {
    uint32_t d;
    asm("{ .reg .u64 t; cvta.to.shared.u64 t, %1; cvt.u32.u64 %0, t; }"
        : "=r"(d) : "l"(smem_dst));
    asm volatile("cp.async.cg.shared.global [%0], [%1], 16;" :: "r"(d), "l"(gsrc));
}
#define CP_COMMIT() asm volatile("cp.async.commit_group;" ::: "memory")
#define CP_WAIT(n)  asm volatile("cp.async.wait_group %0;" :: "n"(n) : "memory")

// ---------------------------------------------------------------------------
// fp32 -> fp16 with scale, vectorized x4
// ---------------------------------------------------------------------------
__global__ void tohalf_kernel(const float* __restrict__ x,
                              __half* __restrict__ y, int n4, float scale) {
    int i = blockIdx.x * blockDim.x + threadIdx.x;
    if (i >= n4) return;
    float4 v = ((const float4*)x)[i];
    __half2* yp = (__half2*)(y + (size_t)i * 4);
    yp[0] = __floats2half2_rn(v.x * scale, v.y * scale);
    yp[1] = __floats2half2_rn(v.z * scale, v.w * scale);
}

// ---------------------------------------------------------------------------
// Partial RoPE (first ROT=32 dims), in place on fp32.
// ---------------------------------------------------------------------------
__global__ void rope_kernel(float* __restrict__ x, const float* __restrict__ ct,
                            const float* __restrict__ st, int nheads, int total) {
    int idx = blockIdx.x * blockDim.x + threadIdx.x;
    if (idx >= total) return;
    int p  = idx & 15;
    int h  = (idx >> 4) % nheads;
    int bs = idx / (16 * nheads);
    float c = ct[bs * 32 + p];
    float s = st[bs * 32 + p];
    size_t base = ((size_t)bs * nheads + h) * 64;
    float x0 = x[base + p];
    float x1 = x[base + p + 16];
    x[base + p]      = x0 * c - x1 * s;
    x[base + p + 16] = x1 * c + x0 * s;
}

// ---------------------------------------------------------------------------
// V transpose to fp16: v[b][s][kvh][d] fp32 -> vht[b][kvh][d][S] half
// ---------------------------------------------------------------------------
__global__ void vT_half_kernel(const float* __restrict__ v,
                               __half* __restrict__ vh) {
    __shared__ float t[32][33];
    const int bkv = blockIdx.z;
    const int b = bkv / NKV, kvh = bkv % NKV;
    const int s0 = blockIdx.x * 32, d0 = blockIdx.y * 32;
    const int tx = threadIdx.x, ty = threadIdx.y;
#pragma unroll
    for (int j = 0; j < 32; j += 8) {
        int s = s0 + ty + j;
        t[ty + j][tx] = v[((size_t)(b * SEQ + s) * NKV + kvh) * HDIM + d0 + tx];
    }
    __syncthreads();
#pragma unroll
    for (int j = 0; j < 32; j += 8) {
        int d = d0 + ty + j;
        size_t o = ((size_t)(b * NKV + kvh) * HDIM + d) * SEQ + s0 + tx;
        vh[o] = __float2half_rn(t[tx][ty + j]);
    }
}

// ---------------------------------------------------------------------------
// Tensor-core GEMM, single-term fp16: C = A @ B^T.
// R5-proven structure: CTA 128x128, 8 warps (2m x 4n), BK=32, 2-stage
// cp.async with prefetch-before-wait, scalar LDS fragment loads.
// ---------------------------------------------------------------------------
#define LDS_STRIDE 40
#define ARR_BYTES  (128 * LDS_STRIDE * 2)     // 10240
#define STAGE_BYTES (2 * ARR_BYTES)           // 20480
#define GEMM_SMEM  (2 * STAGE_BYTES)          // 40960

__global__ __launch_bounds__(256)
void gemm_mma16(const __half* __restrict__ A, const __half* __restrict__ B,
                float* __restrict__ C, int M, int N, int K) {
    extern __shared__ char smem[];

    const int tid = threadIdx.x;
    const int wid = tid >> 5;
    const int lane = tid & 31;
    const int wm = (wid >> 2) * 64;
    const int wn = (wid & 3) * 32;
    const int lr = lane >> 2;
    const int lk = (lane & 3) * 2;

    const int bm = blockIdx.y * 128;
    const int bn = blockIdx.x * 128;

    const int l_row0 = tid >> 2;
    const int l_cw   = (tid & 3) * 8;

    auto stage_ptr = [&](int s, int arr) -> char* {
        return smem + s * STAGE_BYTES + arr * ARR_BYTES;
    };

    auto prefetch = [&](int s, int k0) {
        const __half* gsrc[2] = {A, B};
#pragma unroll
        for (int t = 0; t < 2; t++) {
            const int rb = (t == 0) ? bm : bn;
            char* base = stage_ptr(s, t);
#pragma unroll
            for (int u = 0; u < 2; u++) {
                int row = l_row0 + u * 64;
                cp_async16(base + row * (LDS_STRIDE * 2) + l_cw * 2,
                           gsrc[t] + (size_t)(rb + row) * K + k0 + l_cw);
            }
        }
        CP_COMMIT();
    };

    float acc[4][4][4];
#pragma unroll
    for (int mi = 0; mi < 4; mi++)
#pragma unroll
        for (int ni = 0; ni < 4; ni++)
#pragma unroll
            for (int r = 0; r < 4; r++) acc[mi][ni][r] = 0.f;

    const int nchunk = K / 32;
    prefetch(0, 0);

    for (int ch = 0; ch < nchunk; ch++) {
        const int s = ch & 1;
        if (ch + 1 < nchunk) {
            prefetch(s ^ 1, (ch + 1) * 32);
            CP_WAIT(1);
        } else {
            CP_WAIT(0);
        }
        __syncthreads();

        const __half* sA = (const __half*)stage_ptr(s, 0);
        const __half* sB = (const __half*)stage_ptr(s, 1);

#pragma unroll
        for (int kk = 0; kk < 2; kk++) {
            const int k0 = kk * 16;
            uint32_t bf[4][2];
#pragma unroll
            for (int ni = 0; ni < 4; ni++) {
                int n = wn + ni * 8 + lr;
                bf[ni][0] = *(const uint32_t*)&sB[n * LDS_STRIDE + k0 + lk];
                bf[ni][1] = *(const uint32_t*)&sB[n * LDS_STRIDE + k0 + lk + 8];
            }
#pragma unroll
            for (int mi = 0; mi < 4; mi++) {
                int r0 = wm + mi * 16 + lr;
                uint32_t af[4];
                af[0] = *(const uint32_t*)&sA[(r0    ) * LDS_STRIDE + k0 + lk];
                af[1] = *(const uint32_t*)&sA[(r0 + 8) * LDS_STRIDE + k0 + lk];
                af[2] = *(const uint32_t*)&sA[(r0    ) * LDS_STRIDE + k0 + lk + 8];
                af[3] = *(const uint32_t*)&sA[(r0 + 8) * LDS_STRIDE + k0 + lk + 8];
#pragma unroll
                for (int ni = 0; ni < 4; ni++)
                    mma_f16(acc[mi][ni], af, bf[ni][0], bf[ni][1]);
            }
        }
        __syncthreads();
    }

#pragma unroll
    for (int mi = 0; mi < 4; mi++) {
        int row = bm + wm + mi * 16 + lr;
#pragma unroll
        for (int ni = 0; ni < 4; ni++) {
            int col = bn + wn + ni * 8 + lk;
            *(float2*)(C + (size_t)row * N + col) =
                make_float2(acc[mi][ni][0], acc[mi][ni][1]);
            *(float2*)(C + (size_t)(row + 8) * N + col) =
                make_float2(acc[mi][ni][2], acc[mi][ni][3]);
        }
    }
}

// ---------------------------------------------------------------------------
// Tensor-core flash attention — R10/R11 version (fp16 single-term),
// epilogue writes plain fp16 for the single-term O-projection.
// ---------------------------------------------------------------------------
#define KSTR  72
#define SSTRF 66
#define NEGBIG (-1e30f)
#define FLASH_SMEM (4 * 64 * KSTR * 2 + 64 * SSTRF * 4 + 3 * 64 * 4)

__global__ __launch_bounds__(256)
void flash_tc(const __half* __restrict__ qg, const __half* __restrict__ kg,
              const __half* __restrict__ vg, __half* __restrict__ og) {
    extern __shared__ char smc[];
    __half* sQ = (__half*)smc;
    __half* sK = sQ + 64 * KSTR;
    __half* sV = sK + 64 * KSTR;   // [d][key]
    __half* sP = sV + 64 * KSTR;
    float* sS    = (float*)(sP + 64 * KSTR);
    float* row_m = sS + 64 * SSTRF;
    float* row_l = row_m + 64;
    float* row_a = row_l + 64;

    const int tid  = threadIdx.x;
    const int wid  = tid >> 5;
    const int lane = tid & 31;
    const int wm = (wid >> 2) * 32;
    const int wn = (wid & 3) * 16;
    const int lr = lane >> 2;
    const int lk = (lane & 3) * 2;

    const int qt  = gridDim.x - 1 - blockIdx.x;
    const int bh  = blockIdx.y;
    const int b   = bh >> 5;
    const int h   = bh & 31;
    const int kvh = h >> 2;

#pragma unroll
    for (int u = 0; u < 2; u++) {
        int sl = tid + 256 * u;
        int row = sl >> 3, cw = sl & 7;
        const size_t go = ((size_t)(b * SEQ + qt * 64 + row) * NHEAD + h) * HDIM + cw * 8;
        cp_async16(sQ + row * KSTR + cw * 8, qg + go);
    }
    CP_COMMIT();

    if (tid < 64) { row_m[tid] = NEGBIG; row_l[tid] = 0.f; }

    float oacc[2][2][4];
#pragma unroll
    for (int mi = 0; mi < 2; mi++)
#pragma unroll
        for (int ni = 0; ni < 2; ni++)
#pragma unroll
            for (int r = 0; r < 4; r++) oacc[mi][ni][r] = 0.f;

    for (int kt = 0; kt <= qt; kt++) {
#pragma unroll
        for (int u = 0; u < 2; u++) {
            int sl = tid + 256 * u;
            int row = sl >> 3, cw = sl & 7;
            const size_t gk = ((size_t)(b * SEQ + kt * 64 + row) * NKV + kvh) * HDIM + cw * 8;
            cp_async16(sK + row * KSTR + cw * 8, kg + gk);
            const size_t gv = ((size_t)(b * NKV + kvh) * HDIM + row) * SEQ + kt * 64 + cw * 8;
            cp_async16(sV + row * KSTR + cw * 8, vg + gv);
        }
        CP_COMMIT();
        CP_WAIT(0);
        __syncthreads();

        // ---- S = Q @ K^T ----
        float sacc[2][2][4];
#pragma unroll
        for (int mi = 0; mi < 2; mi++)
#pragma unroll
            for (int ni = 0; ni < 2; ni++)
#pragma unroll
                for (int r = 0; r < 4; r++) sacc[mi][ni][r] = 0.f;

#pragma unroll
        for (int kk = 0; kk < 4; kk++) {
            const int k0 = kk * 16;
            uint32_t kb[2][2];
#pragma unroll
            for (int ni = 0; ni < 2; ni++) {
                int n = wn + ni * 8 + lr;
                kb[ni][0] = *(const uint32_t*)&sK[n * KSTR + k0 + lk];
                kb[ni][1] = *(const uint32_t*)&sK[n * KSTR + k0 + lk + 8];
            }
#pragma unroll
            for (int mi = 0; mi < 2; mi++) {
                int r0 = wm + mi * 16 + lr;
                uint32_t qa[4];
                qa[0] = *(const uint32_t*)&sQ[(r0    ) * KSTR + k0 + lk];
                qa[1] = *(const uint32_t*)&sQ[(r0 + 8) * KSTR + k0 + lk];
                qa[2] = *(const uint32_t*)&sQ[(r0    ) * KSTR + k0 + lk + 8];
                qa[3] = *(const uint32_t*)&sQ[(r0 + 8) * KSTR + k0 + lk + 8];
#pragma unroll
                for (int ni = 0; ni < 2; ni++)
                    mma_f16(sacc[mi][ni], qa, kb[ni][0], kb[ni][1]);
            }
        }

        // ---- mask + store scores ----
        const bool diag = (kt == qt);
#pragma unroll
        for (int mi = 0; mi < 2; mi++) {
#pragma unroll
            for (int ni = 0; ni < 2; ni++) {
                int r = wm + mi * 16 + lr;
                int c = wn + ni * 8 + lk;
                float s0 = sacc[mi][ni][0], s1 = sacc[mi][ni][1];
                float s2 = sacc[mi][ni][2], s3 = sacc[mi][ni][3];
                if (diag) {
                    if (c     > r)     s0 = NEGBIG;
                    if (c + 1 > r)     s1 = NEGBIG;
                    if (c     > r + 8) s2 = NEGBIG;
                    if (c + 1 > r + 8) s3 = NEGBIG;
                }
                *(float2*)&sS[r * SSTRF + c]       = make_float2(s0, s1);
                *(float2*)&sS[(r + 8) * SSTRF + c] = make_float2(s2, s3);
            }
        }
        __syncthreads();

        // ---- online softmax (4 threads/row) ----
        {
            const int row = tid >> 2, seg = tid & 3;
            const float* srow = sS + row * SSTRF + seg * 16;
            float mx = NEGBIG;
#pragma unroll
            for (int j = 0; j < 16; j++) mx = fmaxf(mx, srow[j]);
            mx = fmaxf(mx, __shfl_xor_sync(0xFFFFFFFF, mx, 1));
            mx = fmaxf(mx, __shfl_xor_sync(0xFFFFFFFF, mx, 2));
            const float mprev = row_m[row];
            const float mnew = fmaxf(mprev, mx);
            float sum = 0.f;
            __half* ph = sP + row * KSTR + seg * 16;
#pragma unroll
            for (int j = 0; j < 16; j++) {
                float p = __expf(srow[j] - mnew);
                sum += p;
                ph[j] = __float2half_rn(p);
            }
            sum += __shfl_xor_sync(0xFFFFFFFF, sum, 1);
            sum += __shfl_xor_sync(0xFFFFFFFF, sum, 2);
            if (seg == 0) {
                float alpha = __expf(mprev - mnew);
                row_a[row] = alpha;
                row_l[row] = row_l[row] * alpha + sum;
                row_m[row] = mnew;
            }
        }
        __syncthreads();

        // ---- rescale O, accumulate P @ V ----
#pragma unroll
        for (int mi = 0; mi < 2; mi++) {
            int r0 = wm + mi * 16 + lr;
            float a0 = row_a[r0], a1 = row_a[r0 + 8];
#pragma unroll
            for (int ni = 0; ni < 2; ni++) {
                oacc[mi][ni][0] *= a0; oacc[mi][ni][1] *= a0;
                oacc[mi][ni][2] *= a1; oacc[mi][ni][3] *= a1;
            }
        }
#pragma unroll
        for (int kk = 0; kk < 4; kk++) {
            const int k0 = kk * 16;
            uint32_t vb[2][2];
#pragma unroll
            for (int ni = 0; ni < 2; ni++) {
                int n = wn + ni * 8 + lr;
                vb[ni][0] = *(const uint32_t*)&sV[n * KSTR + k0 + lk];
                vb[ni][1] = *(const uint32_t*)&sV[n * KSTR + k0 + lk + 8];
            }
#pragma unroll
            for (int mi = 0; mi < 2; mi++) {
                int r0 = wm + mi * 16 + lr;
                uint32_t pa[4];
                pa[0] = *(const uint32_t*)&sP[(r0    ) * KSTR + k0 + lk];
                pa[1] = *(const uint32_t*)&sP[(r0 + 8) * KSTR + k0 + lk];
                pa[2] = *(const uint32_t*)&sP[(r0    ) * KSTR + k0 + lk + 8];
                pa[3] = *(const uint32_t*)&sP[(r0 + 8) * KSTR + k0 + lk + 8];
#pragma unroll
                for (int ni = 0; ni < 2; ni++)
                    mma_f16(oacc[mi][ni], pa, vb[ni][0], vb[ni][1]);
            }
        }
        __syncthreads();
    }

    // ---- normalize + write fp16 output [b][s][h][d] ----
#pragma unroll
    for (int mi = 0; mi < 2; mi++) {
        int r = wm + mi * 16 + lr;
        float inv0 = 1.f / row_l[r];
        float inv1 = 1.f / row_l[r + 8];
#pragma unroll
        for (int ni = 0; ni < 2; ni++) {
            int c = wn + ni * 8 + lk;
            size_t o0 = ((size_t)(b * SEQ + qt * 64 + r) * NHEAD + h) * HDIM + c;
            size_t o1 = ((size_t)(b * SEQ + qt * 64 + r + 8) * NHEAD + h) * HDIM + c;
            *(__half2*)(og + o0) = __floats2half2_rn(oacc[mi][ni][0] * inv0,
                                                     oacc[mi][ni][1] * inv0);
            *(__half2*)(og + o1) = __floats2half2_rn(oacc[mi][ni][2] * inv1,
                                                     oacc[mi][ni][3] * inv1);
        }
    }
}

// ---------------------------------------------------------------------------
// Host launcher
// Inputs: 0 hidden 1 cos 2 sin 3 mask(unused) 4 Wq 5 Wk 6 Wv 7 Wo
// ---------------------------------------------------------------------------
extern "C" void kernel_launch(void* const* d_in, const int* in_sizes, int n_in,
                              void* d_out, int out_size) {
    const float* hidden = (const float*)d_in[0];
    const float* cosb   = (const float*)d_in[1];
    const float* sinb   = (const float*)d_in[2];
    const float* Wq     = (const float*)d_in[4];
    const float* Wk     = (const float*)d_in[5];
    const float* Wv     = (const float*)d_in[6];
    const float* Wo     = (const float*)d_in[7];
    float* out = (float*)d_out;

    float *qp, *kp, *vp;
    cudaGetSymbolAddress((void**)&qp, g_q);
    cudaGetSymbolAddress((void**)&kp, g_k);
    cudaGetSymbolAddress((void**)&vp, g_v);

    __half *a16, *o16, *w16q, *w16k, *w16v, *w16o, *qhp, *khp, *vhtp;
    cudaGetSymbolAddress((void**)&a16, g_a16);
    cudaGetSymbolAddress((void**)&o16, g_o16);
    cudaGetSymbolAddress((void**)&w16q, g_w16q);
    cudaGetSymbolAddress((void**)&w16k, g_w16k);
    cudaGetSymbolAddress((void**)&w16v, g_w16v);
    cudaGetSymbolAddress((void**)&w16o, g_w16o);
    cudaGetSymbolAddress((void**)&qhp, g_qh);
    cudaGetSymbolAddress((void**)&khp, g_kh);
    cudaGetSymbolAddress((void**)&vhtp, g_vht);

    const int M = NBATCH * SEQ;  // 4096

    cudaFuncSetAttribute(gemm_mma16, cudaFuncAttributeMaxDynamicSharedMemorySize,
                         GEMM_SMEM);
    cudaFuncSetAttribute(flash_tc, cudaFuncAttributeMaxDynamicSharedMemorySize,
                         FLASH_SMEM);

    // Operand conversions (all single fp16)
    int n4h = (M * HID) / 4;
    tohalf_kernel<<<(n4h + 255) / 256, 256>>>(hidden, a16, n4h, 1.f);
    int n4q = (2048 * 2048) / 4;
    tohalf_kernel<<<(n4q + 255) / 256, 256>>>(Wq, w16q, n4q, 1.f);
    tohalf_kernel<<<(n4q + 255) / 256, 256>>>(Wo, w16o, n4q, 1.f);
    int n4k = (512 * 2048) / 4;
    tohalf_kernel<<<(n4k + 255) / 256, 256>>>(Wk, w16k, n4k, 1.f);
    tohalf_kernel<<<(n4k + 255) / 256, 256>>>(Wv, w16v, n4k, 1.f);

    // QKV projections (fp16 single-term, fp32 out)
    gemm_mma16<<<dim3(2048 / 128, M / 128), 256, GEMM_SMEM>>>(a16, w16q, qp, M, 2048, 2048);
    gemm_mma16<<<dim3(512  / 128, M / 128), 256, GEMM_SMEM>>>(a16, w16k, kp, M, 512, 2048);
    gemm_mma16<<<dim3(512  / 128, M / 128), 256, GEMM_SMEM>>>(a16, w16v, vp, M, 512, 2048);

    // Partial RoPE (fp32, in place)
    int totq = M * NHEAD * 16;
    rope_kernel<<<(totq + 255) / 256, 256>>>(qp, cosb, sinb, NHEAD, totq);
    int totk = M * NKV * 16;
    rope_kernel<<<(totk + 255) / 256, 256>>>(kp, cosb, sinb, NKV, totk);

    // fp16 attention operands (Q scaled by 1/sqrt(D))
    int n4qa = (M * NHEAD * HDIM) / 4;
    tohalf_kernel<<<(n4qa + 255) / 256, 256>>>(qp, qhp, n4qa, 0.125f);
    int n4ka = (M * NKV * HDIM) / 4;
    tohalf_kernel<<<(n4ka + 255) / 256, 256>>>(kp, khp, n4ka, 1.f);
    vT_half_kernel<<<dim3(SEQ / 32, HDIM / 32, NBATCH * NKV), dim3(32, 8)>>>(vp, vhtp);

    // fp16 single-term flash attention -> fp16 out
    flash_tc<<<dim3(SEQ / 64, NBATCH * NHEAD), 256, FLASH_SMEM>>>(qhp, khp, vhtp, o16);

    // Output projection (fp16 single-term)
    gemm_mma16<<<dim3(2048 / 128, M / 128), 256, GEMM_SMEM>>>(o16, w16o, out, M, 2048, 2048);
}

// round 14
// speedup vs baseline: 2.0570x; 1.0071x over previous
#include <cuda_runtime.h>
#include <cuda_fp16.h>
#include <cstdint>
#include <math.h>

// Problem: B=2, S=2048, HID=2048, H=32, KVH=8, D=64, G=4, ROT=32
#define NBATCH 2
#define SEQ    2048
#define HID    2048
#define NHEAD  32
#define NKV    8
#define HDIM   64

// ---------------------------------------------------------------------------
// Scratch (device globals; no allocations allowed)
// ---------------------------------------------------------------------------
__device__ float g_q[NBATCH*SEQ*NHEAD*HDIM];
__device__ float g_k[NBATCH*SEQ*NKV*HDIM];
__device__ float g_v[NBATCH*SEQ*NKV*HDIM];

__device__ __half g_a16[4096*2048];     // hidden fp16
__device__ __half g_o16[4096*2048];     // attn out fp16
__device__ __half g_w16q[2048*2048];
__device__ __half g_w16k[512*2048];
__device__ __half g_w16v[512*2048];
__device__ __half g_w16o[2048*2048];
// fp16 attention operands
__device__ __half g_qh[NBATCH*SEQ*NHEAD*HDIM];
__device__ __half g_kh[NBATCH*SEQ*NKV*HDIM];
__device__ __half g_vht[NBATCH*NKV*HDIM*SEQ];   // [b][kvh][d][S]

// ---------------------------------------------------------------------------
// helpers
// ---------------------------------------------------------------------------
__device__ __forceinline__ void mma_f16(float* c, const uint32_t* a,
                                        uint32_t b0, uint32_t b1) {
    asm volatile(
        "mma.sync.aligned.m16n8k16.row.col.f32.f16.f16.f32 "
        "{%0,%1,%2,%3}, {%4,%5,%6,%7}, {%8,%9}, {%0,%1,%2,%3};"
        : "+f"(c[0]), "+f"(c[1]), "+f"(c[2]), "+f"(c[3])
        : "r"(a[0]), "r"(a[1]), "r"(a[2]), "r"(a[3]), "r"(b0), "r"(b1));
}
__device__ __forceinline__ void cp_async16(void* smem_dst, const void* gsrc) {
    uint32_t d;
    asm("{ .reg .u64 t; cvta.to.shared.u64 t, %1; cvt.u32.u64 %0, t; }"
        : "=r"(d) : "l"(smem_dst));
    asm volatile("cp.async.cg.shared.global [%0], [%1], 16;" :: "r"(d), "l"(gsrc));
}
#define CP_COMMIT() asm volatile("cp.async.commit_group;" ::: "memory")
#define CP_WAIT(n)  asm volatile("cp.async.wait_group %0;" :: "n"(n) : "memory")

// ---------------------------------------------------------------------------
// fp32 -> fp16 with scale, vectorized x4
// ---------------------------------------------------------------------------
__global__ void tohalf_kernel(const float* __restrict__ x,
                              __half* __restrict__ y, int n4, float scale) {
    int i = blockIdx.x * blockDim.x + threadIdx.x;
    if (i >= n4) return;
    float4 v = ((const float4*)x)[i];
    __half2* yp = (__half2*)(y + (size_t)i * 4);
    yp[0] = __floats2half2_rn(v.x * scale, v.y * scale);
    yp[1] = __floats2half2_rn(v.z * scale, v.w * scale);
}

// ---------------------------------------------------------------------------
// Fused partial-RoPE + scale + fp16 convert.
// x fp32 [bs][nheads][64]; one thread per 4-elem quad (R6-proven addressing).
// ---------------------------------------------------------------------------
__global__ void rope_half_kernel(const float* __restrict__ x,
                                 const float* __restrict__ ct,
                                 const float* __restrict__ st,
                                 __half* __restrict__ y,
                                 int nheads, int total4, float scale) {
    int idx = blockIdx.x * blockDim.x + threadIdx.x;
    if (idx >= total4) return;
    int qd = idx & 15;
    int bs = idx / (16 * nheads);
    float4 v = ((const float4*)x)[idx];
    float4 o = v;
    if (qd < 8) {
        int d0 = (qd & 3) * 4;
        float4 p = ((const float4*)x)[idx + (qd < 4 ? 4 : -4)];
        const float* cb = ct + bs * 32 + d0;
        const float* sb = st + bs * 32 + d0;
        if (qd < 4) {
            o.x = v.x * cb[0] - p.x * sb[0];
            o.y = v.y * cb[1] - p.y * sb[1];
            o.z = v.z * cb[2] - p.z * sb[2];
            o.w = v.w * cb[3] - p.w * sb[3];
        } else {
            o.x = v.x * cb[0] + p.x * sb[0];
            o.y = v.y * cb[1] + p.y * sb[1];
            o.z = v.z * cb[2] + p.z * sb[2];
            o.w = v.w * cb[3] + p.w * sb[3];
        }
    }
    __half2* yp = (__half2*)(y + (size_t)idx * 4);
    yp[0] = __floats2half2_rn(o.x * scale, o.y * scale);
    yp[1] = __floats2half2_rn(o.z * scale, o.w * scale);
}

// ---------------------------------------------------------------------------
// V transpose to fp16: v[b][s][kvh][d] fp32 -> vht[b][kvh][d][S] half
// ---------------------------------------------------------------------------
__global__ void vT_half_kernel(const float* __restrict__ v,
                               __half* __restrict__ vh) {
    __shared__ float t[32][33];
    const int bkv = blockIdx.z;
    const int b = bkv / NKV, kvh = bkv % NKV;
    const int s0 = blockIdx.x * 32, d0 = blockIdx.y * 32;
    const int tx = threadIdx.x, ty = threadIdx.y;
#pragma unroll
    for (int j = 0; j < 32; j += 8) {
        int s = s0 + ty + j;
        t[ty + j][tx] = v[((size_t)(b * SEQ + s) * NKV + kvh) * HDIM + d0 + tx];
    }
    __syncthreads();
#pragma unroll
    for (int j = 0; j < 32; j += 8) {
        int d = d0 + ty + j;
        size_t o = ((size_t)(b * NKV + kvh) * HDIM + d) * SEQ + s0 + tx;
        vh[o] = __float2half_rn(t[tx][ty + j]);
    }
}

// ---------------------------------------------------------------------------
// Tensor-core GEMM, single-term fp16: C = A @ B^T.  (R12 proven, untouched)
// ---------------------------------------------------------------------------
#define LDS_STRIDE 40
#define ARR_BYTES  (128 * LDS_STRIDE * 2)     // 10240
#define STAGE_BYTES (2 * ARR_BYTES)           // 20480
#define GEMM_SMEM  (2 * STAGE_BYTES)          // 40960

__global__ __launch_bounds__(256)
void gemm_mma16(const __half* __restrict__ A, const __half* __restrict__ B,
                float* __restrict__ C, int M, int N, int K) {
    extern __shared__ char smem[];

    const int tid = threadIdx.x;
    const int wid = tid >> 5;
    const int lane = tid & 31;
    const int wm = (wid >> 2) * 64;
    const int wn = (wid & 3) * 32;
    const int lr = lane >> 2;
    const int lk = (lane & 3) * 2;

    const int bm = blockIdx.y * 128;
    const int bn = blockIdx.x * 128;

    const int l_row0 = tid >> 2;
    const int l_cw   = (tid & 3) * 8;

    auto stage_ptr = [&](int s, int arr) -> char* {
        return smem + s * STAGE_BYTES + arr * ARR_BYTES;
    };

    auto prefetch = [&](int s, int k0) {
        const __half* gsrc[2] = {A, B};
#pragma unroll
        for (int t = 0; t < 2; t++) {
            const int rb = (t == 0) ? bm : bn;
            char* base = stage_ptr(s, t);
#pragma unroll
            for (int u = 0; u < 2; u++) {
                int row = l_row0 + u * 64;
                cp_async16(base + row * (LDS_STRIDE * 2) + l_cw * 2,
                           gsrc[t] + (size_t)(rb + row) * K + k0 + l_cw);
            }
        }
        CP_COMMIT();
    };

    float acc[4][4][4];
#pragma unroll
    for (int mi = 0; mi < 4; mi++)
#pragma unroll
        for (int ni = 0; ni < 4; ni++)
#pragma unroll
            for (int r = 0; r < 4; r++) acc[mi][ni][r] = 0.f;

    const int nchunk = K / 32;
    prefetch(0, 0);

    for (int ch = 0; ch < nchunk; ch++) {
        const int s = ch & 1;
        if (ch + 1 < nchunk) {
            prefetch(s ^ 1, (ch + 1) * 32);
            CP_WAIT(1);
        } else {
            CP_WAIT(0);
        }
        __syncthreads();

        const __half* sA = (const __half*)stage_ptr(s, 0);
        const __half* sB = (const __half*)stage_ptr(s, 1);

#pragma unroll
        for (int kk = 0; kk < 2; kk++) {
            const int k0 = kk * 16;
            uint32_t bf[4][2];
#pragma unroll
            for (int ni = 0; ni < 4; ni++) {
                int n = wn + ni * 8 + lr;
                bf[ni][0] = *(const uint32_t*)&sB[n * LDS_STRIDE + k0 + lk];
                bf[ni][1] = *(const uint32_t*)&sB[n * LDS_STRIDE + k0 + lk + 8];
            }
#pragma unroll
            for (int mi = 0; mi < 4; mi++) {
                int r0 = wm + mi * 16 + lr;
                uint32_t af[4];
                af[0] = *(const uint32_t*)&sA[(r0    ) * LDS_STRIDE + k0 + lk];
                af[1] = *(const uint32_t*)&sA[(r0 + 8) * LDS_STRIDE + k0 + lk];
                af[2] = *(const uint32_t*)&sA[(r0    ) * LDS_STRIDE + k0 + lk + 8];
                af[3] = *(const uint32_t*)&sA[(r0 + 8) * LDS_STRIDE + k0 + lk + 8];
#pragma unroll
                for (int ni = 0; ni < 4; ni++)
                    mma_f16(acc[mi][ni], af, bf[ni][0], bf[ni][1]);
            }
        }
        __syncthreads();
    }

#pragma unroll
    for (int mi = 0; mi < 4; mi++) {
        int row = bm + wm + mi * 16 + lr;
#pragma unroll
        for (int ni = 0; ni < 4; ni++) {
            int col = bn + wn + ni * 8 + lk;
            *(float2*)(C + (size_t)row * N + col) =
                make_float2(acc[mi][ni][0], acc[mi][ni][1]);
            *(float2*)(C + (size_t)(row + 8) * N + col) =
                make_float2(acc[mi][ni][2], acc[mi][ni][3]);
        }
    }
}

// ---------------------------------------------------------------------------
// Tensor-core flash attention (fp16 single-term) with 2-stage K/V pipeline.
// Grid (32, 64). 256 threads, 8 warps 2m x 4n. Tile 64 q x 64 keys.
// ---------------------------------------------------------------------------
#define KSTR  72
#define SSTRF 66
#define NEGBIG (-1e30f)
// smem: Q + 2*K + 2*V + P (6 half arrays) + scores + row stats
#define FLASH_SMEM (6 * 64 * KSTR * 2 + 64 * SSTRF * 4 + 3 * 64 * 4)

__global__ __launch_bounds__(256)
void flash_tc(const __half* __restrict__ qg, const __half* __restrict__ kg,
              const __half* __restrict__ vg, __half* __restrict__ og) {
    extern __shared__ char smc[];
    __half* sQ  = (__half*)smc;
    __half* sK0 = sQ  + 64 * KSTR;
    __half* sK1 = sK0 + 64 * KSTR;
    __half* sV0 = sK1 + 64 * KSTR;
    __half* sV1 = sV0 + 64 * KSTR;
    __half* sP  = sV1 + 64 * KSTR;
    float* sS    = (float*)(sP + 64 * KSTR);
    float* row_m = sS + 64 * SSTRF;
    float* row_l = row_m + 64;
    float* row_a = row_l + 64;

    const int tid  = threadIdx.x;
    const int wid  = tid >> 5;
    const int lane = tid & 31;
    const int wm = (wid >> 2) * 32;
    const int wn = (wid & 3) * 16;
    const int lr = lane >> 2;
    const int lk = (lane & 3) * 2;

    const int qt  = gridDim.x - 1 - blockIdx.x;
    const int bh  = blockIdx.y;
    const int b   = bh >> 5;
    const int h   = bh & 31;
    const int kvh = h >> 2;

    // loader mapping
    const int l_row = tid >> 3;          // with +32 for second half
    const int l_cw  = (tid & 7) * 8;

    // Q tile load (group 0)
#pragma unroll
    for (int u = 0; u < 2; u++) {
        int row = l_row + u * 32;
        const size_t go = ((size_t)(b * SEQ + qt * 64 + row) * NHEAD + h) * HDIM + l_cw;
        cp_async16(sQ + row * KSTR + l_cw, qg + go);
    }
    CP_COMMIT();

    auto loadKV = [&](int kt, int s) {
        __half* dK = s ? sK1 : sK0;
        __half* dV = s ? sV1 : sV0;
#pragma unroll
        for (int u = 0; u < 2; u++) {
            int row = l_row + u * 32;
            const size_t gk = ((size_t)(b * SEQ + kt * 64 + row) * NKV + kvh) * HDIM + l_cw;
            cp_async16(dK + row * KSTR + l_cw, kg + gk);
            const size_t gv = ((size_t)(b * NKV + kvh) * HDIM + row) * SEQ + kt * 64 + l_cw;
            cp_async16(dV + row * KSTR + l_cw, vg + gv);
        }
        CP_COMMIT();
    };

    loadKV(0, 0);   // group 1

    if (tid < 64) { row_m[tid] = NEGBIG; row_l[tid] = 0.f; }

    float oacc[2][2][4];
#pragma unroll
    for (int mi = 0; mi < 2; mi++)
#pragma unroll
        for (int ni = 0; ni < 2; ni++)
#pragma unroll
            for (int r = 0; r < 4; r++) oacc[mi][ni][r] = 0.f;

    for (int kt = 0; kt <= qt; kt++) {
        const int s = kt & 1;
        if (kt + 1 <= qt) {
            loadKV(kt + 1, s ^ 1);
            CP_WAIT(1);
        } else {
            CP_WAIT(0);
        }
        __syncthreads();

        const __half* sK = s ? sK1 : sK0;
        const __half* sV = s ? sV1 : sV0;

        // ---- S = Q @ K^T ----
        float sacc[2][2][4];
#pragma unroll
        for (int mi = 0; mi < 2; mi++)
#pragma unroll
            for (int ni = 0; ni < 2; ni++)
#pragma unroll
                for (int r = 0; r < 4; r++) sacc[mi][ni][r] = 0.f;

#pragma unroll
        for (int kk = 0; kk < 4; kk++) {
            const int k0 = kk * 16;
            uint32_t kb[2][2];
#pragma unroll
            for (int ni = 0; ni < 2; ni++) {
                int n = wn + ni * 8 + lr;
                kb[ni][0] = *(const uint32_t*)&sK[n * KSTR + k0 + lk];
                kb[ni][1] = *(const uint32_t*)&sK[n * KSTR + k0 + lk + 8];
            }
#pragma unroll
            for (int mi = 0; mi < 2; mi++) {
                int r0 = wm + mi * 16 + lr;
                uint32_t qa[4];
                qa[0] = *(const uint32_t*)&sQ[(r0    ) * KSTR + k0 + lk];
                qa[1] = *(const uint32_t*)&sQ[(r0 + 8) * KSTR + k0 + lk];
                qa[2] = *(const uint32_t*)&sQ[(r0    ) * KSTR + k0 + lk + 8];
                qa[3] = *(const uint32_t*)&sQ[(r0 + 8) * KSTR + k0 + lk + 8];
#pragma unroll
                for (int ni = 0; ni < 2; ni++)
                    mma_f16(sacc[mi][ni], qa, kb[ni][0], kb[ni][1]);
            }
        }

        // ---- mask + store scores ----
        const bool diag = (kt == qt);
#pragma unroll
        for (int mi = 0; mi < 2; mi++) {
#pragma unroll
            for (int ni = 0; ni < 2; ni++) {
                int r = wm + mi * 16 + lr;
                int c = wn + ni * 8 + lk;
                float s0 = sacc[mi][ni][0], s1 = sacc[mi][ni][1];
                float s2 = sacc[mi][ni][2], s3 = sacc[mi][ni][3];
                if (diag) {
                    if (c     > r)     s0 = NEGBIG;
                    if (c + 1 > r)     s1 = NEGBIG;
                    if (c     > r + 8) s2 = NEGBIG;
                    if (c + 1 > r + 8) s3 = NEGBIG;
                }
                *(float2*)&sS[r * SSTRF + c]       = make_float2(s0, s1);
                *(float2*)&sS[(r + 8) * SSTRF + c] = make_float2(s2, s3);
            }
        }
        __syncthreads();

        // ---- online softmax (4 threads/row) ----
        {
            const int row = tid >> 2, seg = tid & 3;
            const float* srow = sS + row * SSTRF + seg * 16;
            float mx = NEGBIG;
#pragma unroll
            for (int j = 0; j < 16; j++) mx = fmaxf(mx, srow[j]);
            mx = fmaxf(mx, __shfl_xor_sync(0xFFFFFFFF, mx, 1));
            mx = fmaxf(mx, __shfl_xor_sync(0xFFFFFFFF, mx, 2));
            const float mprev = row_m[row];
            const float mnew = fmaxf(mprev, mx);
            float sum = 0.f;
            __half* ph = sP + row * KSTR + seg * 16;
#pragma unroll
            for (int j = 0; j < 16; j++) {
                float p = __expf(srow[j] - mnew);
                sum += p;
                ph[j] = __float2half_rn(p);
            }
            sum += __shfl_xor_sync(0xFFFFFFFF, sum, 1);
            sum += __shfl_xor_sync(0xFFFFFFFF, sum, 2);
            if (seg == 0) {
                float alpha = __expf(mprev - mnew);
                row_a[row] = alpha;
                row_l[row] = row_l[row] * alpha + sum;
                row_m[row] = mnew;
            }
        }
        __syncthreads();

        // ---- rescale O, accumulate P @ V ----
#pragma unroll
        for (int mi = 0; mi < 2; mi++) {
            int r0 = wm + mi * 16 + lr;
            float a0 = row_a[r0], a1 = row_a[r0 + 8];
#pragma unroll
            for (int ni = 0; ni < 2; ni++) {
                oacc[mi][ni][0] *= a0; oacc[mi][ni][1] *= a0;
                oacc[mi][ni][2] *= a1; oacc[mi][ni][3] *= a1;
            }
        }
#pragma unroll
        for (int kk = 0; kk < 4; kk++) {
            const int k0 = kk * 16;
            uint32_t vb[2][2];
#pragma unroll
            for (int ni = 0; ni < 2; ni++) {
                int n = wn + ni * 8 + lr;
                vb[ni][0] = *(const uint32_t*)&sV[n * KSTR + k0 + lk];
                vb[ni][1] = *(const uint32_t*)&sV[n * KSTR + k0 + lk + 8];
            }
#pragma unroll
            for (int mi = 0; mi < 2; mi++) {
                int r0 = wm + mi * 16 + lr;
                uint32_t pa[4];
                pa[0] = *(const uint32_t*)&sP[(r0    ) * KSTR + k0 + lk];
                pa[1] = *(const uint32_t*)&sP[(r0 + 8) * KSTR + k0 + lk];
                pa[2] = *(const uint32_t*)&sP[(r0    ) * KSTR + k0 + lk + 8];
                pa[3] = *(const uint32_t*)&sP[(r0 + 8) * KSTR + k0 + lk + 8];
#pragma unroll
                for (int ni = 0; ni < 2; ni++)
                    mma_f16(oacc[mi][ni], pa, vb[ni][0], vb[ni][1]);
            }
        }
        __syncthreads();
    }

    // ---- normalize + write fp16 output [b][s][h][d] ----
#pragma unroll
    for (int mi = 0; mi < 2; mi++) {
        int r = wm + mi * 16 + lr;
        float inv0 = 1.f / row_l[r];
        float inv1 = 1.f / row_l[r + 8];
#pragma unroll
        for (int ni = 0; ni < 2; ni++) {
            int c = wn + ni * 8 + lk;
            size_t o0 = ((size_t)(b * SEQ + qt * 64 + r) * NHEAD + h) * HDIM + c;
            size_t o1 = ((size_t)(b * SEQ + qt * 64 + r + 8) * NHEAD + h) * HDIM + c;
            *(__half2*)(og + o0) = __floats2half2_rn(oacc[mi][ni][0] * inv0,
                                                     oacc[mi][ni][1] * inv0);
            *(__half2*)(og + o1) = __floats2half2_rn(oacc[mi][ni][2] * inv1,
                                                     oacc[mi][ni][3] * inv1);
        }
    }
}

// ---------------------------------------------------------------------------
// Host launcher
// Inputs: 0 hidden 1 cos 2 sin 3 mask(unused) 4 Wq 5 Wk 6 Wv 7 Wo
// ---------------------------------------------------------------------------
extern "C" void kernel_launch(void* const* d_in, const int* in_sizes, int n_in,
                              void* d_out, int out_size) {
    const float* hidden = (const float*)d_in[0];
    const float* cosb   = (const float*)d_in[1];
    const float* sinb   = (const float*)d_in[2];
    const float* Wq     = (const float*)d_in[4];
    const float* Wk     = (const float*)d_in[5];
    const float* Wv     = (const float*)d_in[6];
    const float* Wo     = (const float*)d_in[7];
    float* out = (float*)d_out;

    float *qp, *kp, *vp;
    cudaGetSymbolAddress((void**)&qp, g_q);
    cudaGetSymbolAddress((void**)&kp, g_k);
    cudaGetSymbolAddress((void**)&vp, g_v);

    __half *a16, *o16, *w16q, *w16k, *w16v, *w16o, *qhp, *khp, *vhtp;
    cudaGetSymbolAddress((void**)&a16, g_a16);
    cudaGetSymbolAddress((void**)&o16, g_o16);
    cudaGetSymbolAddress((void**)&w16q, g_w16q);
    cudaGetSymbolAddress((void**)&w16k, g_w16k);
    cudaGetSymbolAddress((void**)&w16v, g_w16v);
    cudaGetSymbolAddress((void**)&w16o, g_w16o);
    cudaGetSymbolAddress((void**)&qhp, g_qh);
    cudaGetSymbolAddress((void**)&khp, g_kh);
    cudaGetSymbolAddress((void**)&vhtp, g_vht);

    const int M = NBATCH * SEQ;  // 4096

    cudaFuncSetAttribute(gemm_mma16, cudaFuncAttributeMaxDynamicSharedMemorySize,
                         GEMM_SMEM);
    cudaFuncSetAttribute(flash_tc, cudaFuncAttributeMaxDynamicSharedMemorySize,
                         FLASH_SMEM);

    // Operand conversions (all single fp16)
    int n4h = (M * HID) / 4;
    tohalf_kernel<<<(n4h + 255) / 256, 256>>>(hidden, a16, n4h, 1.f);
    int n4q = (2048 * 2048) / 4;
    tohalf_kernel<<<(n4q + 255) / 256, 256>>>(Wq, w16q, n4q, 1.f);
    tohalf_kernel<<<(n4q + 255) / 256, 256>>>(Wo, w16o, n4q, 1.f);
    int n4k = (512 * 2048) / 4;
    tohalf_kernel<<<(n4k + 255) / 256, 256>>>(Wk, w16k, n4k, 1.f);
    tohalf_kernel<<<(n4k + 255) / 256, 256>>>(Wv, w16v, n4k, 1.f);

    // QKV projections (fp16 single-term, fp32 out)
    gemm_mma16<<<dim3(2048 / 128, M / 128), 256, GEMM_SMEM>>>(a16, w16q, qp, M, 2048, 2048);
    gemm_mma16<<<dim3(512  / 128, M / 128), 256, GEMM_SMEM>>>(a16, w16k, kp, M, 512, 2048);
    gemm_mma16<<<dim3(512  / 128, M / 128), 256, GEMM_SMEM>>>(a16, w16v, vp, M, 512, 2048);

    // Fused RoPE + scale + fp16 convert (Q scaled by 1/sqrt(D))
    int tq4 = M * NHEAD * 16;
    rope_half_kernel<<<(tq4 + 255) / 256, 256>>>(qp, cosb, sinb, qhp, NHEAD, tq4, 0.125f);
    int tk4 = M * NKV * 16;
    rope_half_kernel<<<(tk4 + 255) / 256, 256>>>(kp, cosb, sinb, khp, NKV, tk4, 1.f);

    vT_half_kernel<<<dim3(SEQ / 32, HDIM / 32, NBATCH * NKV), dim3(32, 8)>>>(vp, vhtp);

    // fp16 single-term flash attention (2-stage K/V pipeline) -> fp16 out
    flash_tc<<<dim3(SEQ / 64, NBATCH * NHEAD), 256, FLASH_SMEM>>>(qhp, khp, vhtp, o16);

    // Output projection (fp16 single-term)
    gemm_mma16<<<dim3(2048 / 128, M / 128), 256, GEMM_SMEM>>>(o16, w16o, out, M, 2048, 2048);
}